// round 10
// baseline (speedup 1.0000x reference)
#include <cuda_runtime.h>
#include <cuda_bf16.h>
#include <cstdint>

// Problem constants
#define B_  2
#define T_  2048
#define D_  2048
#define H_  16
#define HKV_ 4
#define DH_ 128
#define M_  (B_*T_)
#define NQ_ (H_*DH_)
#define NKV_ (HKV_*DH_)

// fp32 scratch
__device__ float g_q[(size_t)M_ * NQ_];
__device__ float g_k[(size_t)M_ * NKV_];
__device__ float g_v[(size_t)M_ * NKV_];

// bf16 split scratch
__device__ __nv_bfloat16 g_xhi[(size_t)M_ * D_],  g_xlo[(size_t)M_ * D_];
__device__ __nv_bfloat16 g_qwhi[(size_t)NQ_ * D_], g_qwlo[(size_t)NQ_ * D_];
__device__ __nv_bfloat16 g_kwhi[(size_t)NKV_ * D_], g_kwlo[(size_t)NKV_ * D_];
__device__ __nv_bfloat16 g_vwhi[(size_t)NKV_ * D_], g_vwlo[(size_t)NKV_ * D_];
__device__ __nv_bfloat16 g_owhi[(size_t)D_ * D_],  g_owlo[(size_t)D_ * D_];
__device__ __nv_bfloat16 g_ahi[(size_t)M_ * NQ_],  g_alo[(size_t)M_ * NQ_];

// ---------------------------------------------------------------------------
// PTX helpers (compute_103-safe: cp.async, ldmatrix, mma.sync only)
// ---------------------------------------------------------------------------
__device__ __forceinline__ void cp_async16(uint32_t s, const void* g) {
    asm volatile("cp.async.cg.shared.global [%0], [%1], 16;\n" :: "r"(s), "l"(g));
}
__device__ __forceinline__ void cp_commit() {
    asm volatile("cp.async.commit_group;\n");
}
template<int N> __device__ __forceinline__ void cp_wait() {
    asm volatile("cp.async.wait_group %0;\n" :: "n"(N));
}
__device__ __forceinline__ void ldsm_x4(uint32_t& r0, uint32_t& r1,
                                        uint32_t& r2, uint32_t& r3, uint32_t a) {
    asm volatile("ldmatrix.sync.aligned.m8n8.x4.shared.b16 {%0,%1,%2,%3}, [%4];\n"
                 : "=r"(r0), "=r"(r1), "=r"(r2), "=r"(r3) : "r"(a));
}
__device__ __forceinline__ void mma_bf16(float* d, const uint32_t* a,
                                         uint32_t b0, uint32_t b1) {
    asm volatile(
        "mma.sync.aligned.m16n8k16.row.col.f32.bf16.bf16.f32 "
        "{%0,%1,%2,%3},{%4,%5,%6,%7},{%8,%9},{%0,%1,%2,%3};\n"
        : "+f"(d[0]), "+f"(d[1]), "+f"(d[2]), "+f"(d[3])
        : "r"(a[0]), "r"(a[1]), "r"(a[2]), "r"(a[3]), "r"(b0), "r"(b1));
}
__device__ __forceinline__ void mma_tf32(float* d, const uint32_t* a,
                                         uint32_t b0, uint32_t b1) {
    asm volatile(
        "mma.sync.aligned.m16n8k8.row.col.f32.tf32.tf32.f32 "
        "{%0,%1,%2,%3},{%4,%5,%6,%7},{%8,%9},{%0,%1,%2,%3};\n"
        : "+f"(d[0]), "+f"(d[1]), "+f"(d[2]), "+f"(d[3])
        : "r"(a[0]), "r"(a[1]), "r"(a[2]), "r"(a[3]), "r"(b0), "r"(b1));
}
__device__ __forceinline__ uint32_t f2tf32(float x) {
    uint32_t r;
    asm("cvt.rna.tf32.f32 %0, %1;" : "=r"(r) : "f"(x));
    return r;
}
__device__ __forceinline__ float tf32r(float x) { return __uint_as_float(f2tf32(x)); }
__device__ __forceinline__ float fexp2(float x) {
    float y;
    asm("ex2.approx.ftz.f32 %0, %1;" : "=f"(y) : "f"(x));
    return y;
}

// ---------------------------------------------------------------------------
// Split fp32 -> bf16 hi + lo
// ---------------------------------------------------------------------------
__global__ __launch_bounds__(256) void split_kernel(
    const float* __restrict__ in, __nv_bfloat16* __restrict__ hi,
    __nv_bfloat16* __restrict__ lo, int n)
{
    int i = blockIdx.x * blockDim.x + threadIdx.x;
    if (i < n) {
        float v = in[i];
        __nv_bfloat16 h = __float2bfloat16(v);
        hi[i] = h;
        lo[i] = __float2bfloat16(v - __bfloat162float(h));
    }
}

// ---------------------------------------------------------------------------
// bf16x3 NT GEMM:  C[m,n] = sum_k A[m,k] * W[n,k]   (fp32 out)
//   C ~= Ahi*Whi + Ahi*Wlo + Alo*Whi
// 128x128 tile, BK=32, 256 threads (8 warps, 2x4), warp tile 64x32,
// mma.m16n8k16, cp.async 2-stage pipeline, ldmatrix, 80B smem row stride.
// __launch_bounds__(256,2): force 2 CTAs/SM (regs<=128) to cover latency.
// ---------------------------------------------------------------------------
#define BK_G   32
#define LDSR   40
#define TILE_E (128*LDSR)
#define TILE_B (TILE_E*2)
#define STAGE_B (4*TILE_B)
#define GEMM_SMEM (2*STAGE_B)

__device__ __forceinline__ void gemm_load_stage(
    uint32_t sa, const __nv_bfloat16* Ahi, const __nv_bfloat16* Alo,
    const __nv_bfloat16* Whi, const __nv_bfloat16* Wlo,
    int bm, int bn, int K, int k0, int tid)
{
#pragma unroll
    for (int half = 0; half < 2; half++) {
        const int idx = tid + half * 256;
        const int row = idx >> 2;
        const int c8  = (idx & 3) << 3;
        const size_t ga = (size_t)(bm + row) * K + k0 + c8;
        const size_t gw = (size_t)(bn + row) * K + k0 + c8;
        const uint32_t so = (uint32_t)(row * LDSR + c8) * 2;
        cp_async16(sa +            so, Ahi + ga);
        cp_async16(sa + TILE_B   + so, Alo + ga);
        cp_async16(sa + 2*TILE_B + so, Whi + gw);
        cp_async16(sa + 3*TILE_B + so, Wlo + gw);
    }
}

__global__ __launch_bounds__(256, 2) void gemm_bf16x3(
    const __nv_bfloat16* __restrict__ Ahi, const __nv_bfloat16* __restrict__ Alo,
    const __nv_bfloat16* __restrict__ Whi, const __nv_bfloat16* __restrict__ Wlo,
    float* __restrict__ C, int M, int N, int K)
{
    extern __shared__ __nv_bfloat16 smg[];
    const int tid  = threadIdx.x;
    const int warp = tid >> 5, lane = tid & 31;
    const int wm = (warp >> 2) * 64;
    const int wn = (warp & 3) * 32;
    const int bm = blockIdx.y * 128;
    const int bn = blockIdx.x * 128;
    const uint32_t sbase = (uint32_t)__cvta_generic_to_shared(smg);

    float acc[4][4][4];
#pragma unroll
    for (int i = 0; i < 4; i++)
#pragma unroll
        for (int j = 0; j < 4; j++)
#pragma unroll
            for (int r = 0; r < 4; r++) acc[i][j][r] = 0.f;

    const int arow = (lane & 7) + ((lane >> 3) & 1) * 8;
    const int acb  = ((lane >> 4) & 1) * 16;
    const int brow = (lane & 7) + ((lane >> 4) & 1) * 8;
    const int bcb  = ((lane >> 3) & 1) * 16;

    gemm_load_stage(sbase, Ahi, Alo, Whi, Wlo, bm, bn, K, 0, tid);
    cp_commit();

    const int NC = K / BK_G;
    for (int c = 0; c < NC; c++) {
        if (c + 1 < NC) {
            gemm_load_stage(sbase + ((c + 1) & 1) * STAGE_B,
                            Ahi, Alo, Whi, Wlo, bm, bn, K, (c + 1) * BK_G, tid);
            cp_commit();
            cp_wait<1>();
        } else {
            cp_wait<0>();
        }
        __syncthreads();

        const uint32_t base = sbase + (c & 1) * STAGE_B;
        const uint32_t aAhi = base;
        const uint32_t aAlo = base + TILE_B;
        const uint32_t aWhi = base + 2*TILE_B;
        const uint32_t aWlo = base + 3*TILE_B;

#pragma unroll
        for (int kh = 0; kh < 2; kh++) {
            const int kb = kh * 32;
            uint32_t bhi[4][2], blo[4][2];
#pragma unroll
            for (int jj = 0; jj < 2; jj++) {
                uint32_t ad = aWhi + (uint32_t)((wn + jj*16 + brow) * LDSR) * 2 + bcb + kb;
                ldsm_x4(bhi[2*jj][0], bhi[2*jj][1], bhi[2*jj+1][0], bhi[2*jj+1][1], ad);
                ad = aWlo + (uint32_t)((wn + jj*16 + brow) * LDSR) * 2 + bcb + kb;
                ldsm_x4(blo[2*jj][0], blo[2*jj][1], blo[2*jj+1][0], blo[2*jj+1][1], ad);
            }
            uint32_t a[4][4];
#pragma unroll
            for (int i = 0; i < 4; i++) {
                uint32_t ad = aAhi + (uint32_t)((wm + i*16 + arow) * LDSR) * 2 + acb + kb;
                ldsm_x4(a[i][0], a[i][1], a[i][2], a[i][3], ad);
            }
#pragma unroll
            for (int i = 0; i < 4; i++)
#pragma unroll
                for (int j = 0; j < 4; j++) {
                    mma_bf16(acc[i][j], a[i], bhi[j][0], bhi[j][1]);
                    mma_bf16(acc[i][j], a[i], blo[j][0], blo[j][1]);
                }
#pragma unroll
            for (int i = 0; i < 4; i++) {
                uint32_t ad = aAlo + (uint32_t)((wm + i*16 + arow) * LDSR) * 2 + acb + kb;
                ldsm_x4(a[i][0], a[i][1], a[i][2], a[i][3], ad);
            }
#pragma unroll
            for (int i = 0; i < 4; i++)
#pragma unroll
                for (int j = 0; j < 4; j++)
                    mma_bf16(acc[i][j], a[i], bhi[j][0], bhi[j][1]);
        }
        __syncthreads();
    }

    const int er = lane >> 2, ec = (lane & 3) * 2;
#pragma unroll
    for (int i = 0; i < 4; i++)
#pragma unroll
        for (int j = 0; j < 4; j++) {
            float* p0 = C + (size_t)(bm + wm + 16*i + er) * N + bn + wn + 8*j + ec;
            float* p1 = p0 + (size_t)8 * N;
            *(float2*)p0 = make_float2(acc[i][j][0], acc[i][j][1]);
            *(float2*)p1 = make_float2(acc[i][j][2], acc[i][j][3]);
        }
}

// ---------------------------------------------------------------------------
// RoPE + scale fold + round-to-TF32 in place on q, k, v.
// ---------------------------------------------------------------------------
__global__ __launch_bounds__(256) void rope_tf32(
    float* __restrict__ q, float* __restrict__ k, float* __restrict__ v,
    const float* __restrict__ cosb, const float* __restrict__ sinb,
    const float* __restrict__ temp)
{
    const int token = blockIdx.x;
    const int t = token & (T_ - 1);
    const float SC = 0.08838834764831845f * 1.4426950408889634f;
    for (int s = threadIdx.x; s < 1536; s += blockDim.x) {
        const int head = s >> 6;
        const int i = s & 63;
        float* base;
        float scale = 1.0f;
        bool dorope = true;
        if (head < 16) {
            base = q + ((size_t)token * H_ + head) * DH_;
            scale = temp[head] * SC;
        } else if (head < 20) {
            base = k + ((size_t)token * HKV_ + (head - 16)) * DH_;
        } else {
            base = v + ((size_t)token * HKV_ + (head - 20)) * DH_;
            dorope = false;
        }
        if (dorope && i < 32) {
            const float c  = cosb[t*32 + i];
            const float sn = sinb[t*32 + i];
            const float x1 = base[2*i];
            const float x2 = base[2*i + 1];
            base[2*i]     = tf32r((x1*c - x2*sn) * scale);
            base[2*i + 1] = tf32r((x1*sn + x2*c) * scale);
        } else {
            const int d = dorope ? 64 + (i - 32) * 2 : i * 2;
            base[d]     = tf32r(base[d] * scale);
            base[d + 1] = tf32r(base[d + 1] * scale);
        }
    }
}

// ---------------------------------------------------------------------------
// TF32 tensor-core causal GQA flash attention (proven round-8 kernel).
// ---------------------------------------------------------------------------
#define KOFF0 0
#define KOFF1 8448
#define VOFF0 16896
#define VOFF1 25600
#define POFF  34304
#define ATTN_SMEM_B ((POFF + 8704) * 4)

__global__ __launch_bounds__(256, 1) void attn_tc(
    const float* __restrict__ Qg, const float* __restrict__ Kg,
    const float* __restrict__ Vg,
    __nv_bfloat16* __restrict__ Ahi, __nv_bfloat16* __restrict__ Alo)
{
    extern __shared__ float sm[];
    const uint32_t sbase = (uint32_t)__cvta_generic_to_shared(sm);
    const int qt = 15 - blockIdx.x;
    const int h = blockIdx.y, b = blockIdx.z;
    const int kvh = h >> 2;
    const int tid = threadIdx.x;
    const int warp = tid >> 5, lane = tid & 31;
    const int g4 = lane >> 2, c4 = lane & 3;
    const int qrow0 = qt * 128 + warp * 16;
    const int nk = 2 * qt + 2;

    uint32_t qf[16][4];
    {
        const float* Q0 = Qg + ((size_t)(b*T_ + qrow0 + g4)*H_ + h)*DH_;
        const float* Q1 = Q0 + (size_t)8*H_*DH_;
#pragma unroll
        for (int kc = 0; kc < 16; kc++) {
            const int c0 = kc*8 + c4;
            qf[kc][0] = __float_as_uint(__ldg(Q0 + c0));
            qf[kc][1] = __float_as_uint(__ldg(Q1 + c0));
            qf[kc][2] = __float_as_uint(__ldg(Q0 + c0 + 4));
            qf[kc][3] = __float_as_uint(__ldg(Q1 + c0 + 4));
        }
    }

    float o[16][4];
#pragma unroll
    for (int dt = 0; dt < 16; dt++)
#pragma unroll
        for (int r = 0; r < 4; r++) o[dt][r] = 0.f;
    float m0 = -1e30f, m1 = -1e30f, l0 = 0.f, l1 = 0.f;

    float* Ps = sm + POFF + warp * 1088;

    {
        const size_t kvoff = ((size_t)(b*T_)*HKV_ + kvh)*DH_;
#pragma unroll
        for (int i = 0; i < 8; i++) {
            const int idx = tid + i*256, row = idx >> 5, cc = (idx & 31)*4;
            cp_async16(sbase + (uint32_t)(KOFF0 + row*132 + cc)*4,
                       Kg + kvoff + (size_t)row*NKV_ + cc);
        }
        cp_commit();
#pragma unroll
        for (int i = 0; i < 8; i++) {
            const int idx = tid + i*256, row = idx >> 5, cc = (idx & 31)*4;
            cp_async16(sbase + (uint32_t)(VOFF0 + row*136 + cc)*4,
                       Vg + kvoff + (size_t)row*NKV_ + cc);
        }
        cp_commit();
    }

    for (int kt = 0; kt < nk; kt++) {
        const int kc0 = kt * 64;
        const bool skip = (kc0 > qrow0 + 15);
        cp_wait<1>();
        __syncthreads();

        float sacc[8][4];
        if (!skip) {
#pragma unroll
            for (int nt = 0; nt < 8; nt++)
#pragma unroll
                for (int r = 0; r < 4; r++) sacc[nt][r] = 0.f;
            const float* Ksm = sm + ((kt & 1) ? KOFF1 : KOFF0);
#pragma unroll
            for (int kc = 0; kc < 16; kc++) {
                const int dk = kc*8 + c4;
#pragma unroll
                for (int nt = 0; nt < 8; nt++) {
                    const float* kp = Ksm + (nt*8 + g4)*132 + dk;
                    mma_tf32(sacc[nt], qf[kc],
                             __float_as_uint(kp[0]), __float_as_uint(kp[4]));
                }
            }
        }

        if (kt + 1 < nk) {
            const size_t kvoff = ((size_t)(b*T_ + kc0 + 64)*HKV_ + kvh)*DH_;
            const uint32_t kb = sbase + (uint32_t)(((kt+1)&1) ? KOFF1 : KOFF0)*4;
#pragma unroll
            for (int i = 0; i < 8; i++) {
                const int idx = tid + i*256, row = idx >> 5, cc = (idx & 31)*4;
                cp_async16(kb + (uint32_t)(row*132 + cc)*4,
                           Kg + kvoff + (size_t)row*NKV_ + cc);
            }
            cp_commit();
        }

        if (!skip) {
            if (kc0 + 63 > qrow0) {
#pragma unroll
                for (int nt = 0; nt < 8; nt++) {
                    const int cc = kc0 + nt*8 + 2*c4;
                    const int r0 = qrow0 + g4, r1 = r0 + 8;
                    if (cc     > r0) sacc[nt][0] = -1e30f;
                    if (cc + 1 > r0) sacc[nt][1] = -1e30f;
                    if (cc     > r1) sacc[nt][2] = -1e30f;
                    if (cc + 1 > r1) sacc[nt][3] = -1e30f;
                }
            }
            float rm0 = -1e30f, rm1 = -1e30f;
#pragma unroll
            for (int nt = 0; nt < 8; nt++) {
                rm0 = fmaxf(rm0, fmaxf(sacc[nt][0], sacc[nt][1]));
                rm1 = fmaxf(rm1, fmaxf(sacc[nt][2], sacc[nt][3]));
            }
#pragma unroll
            for (int off = 1; off <= 2; off <<= 1) {
                rm0 = fmaxf(rm0, __shfl_xor_sync(0xffffffffu, rm0, off));
                rm1 = fmaxf(rm1, __shfl_xor_sync(0xffffffffu, rm1, off));
            }
            const float mn0 = fmaxf(m0, rm0), mn1 = fmaxf(m1, rm1);
            const float a0 = fexp2(m0 - mn0), a1 = fexp2(m1 - mn1);
            m0 = mn0; m1 = mn1;
            float rs0 = 0.f, rs1 = 0.f;
#pragma unroll
            for (int nt = 0; nt < 8; nt++) {
                float p0 = fexp2(sacc[nt][0] - mn0);
                float p1 = fexp2(sacc[nt][1] - mn0);
                float p2 = fexp2(sacc[nt][2] - mn1);
                float p3 = fexp2(sacc[nt][3] - mn1);
                rs0 += p0 + p1; rs1 += p2 + p3;
                float* pr = Ps + g4*68 + nt*8 + 2*c4;
                *(float2*)pr = make_float2(__uint_as_float(f2tf32(p0)),
                                           __uint_as_float(f2tf32(p1)));
                *(float2*)(pr + 8*68) = make_float2(__uint_as_float(f2tf32(p2)),
                                                    __uint_as_float(f2tf32(p3)));
            }
#pragma unroll
            for (int off = 1; off <= 2; off <<= 1) {
                rs0 += __shfl_xor_sync(0xffffffffu, rs0, off);
                rs1 += __shfl_xor_sync(0xffffffffu, rs1, off);
            }
            l0 = l0 * a0 + rs0;
            l1 = l1 * a1 + rs1;
#pragma unroll
            for (int dt = 0; dt < 16; dt++) {
                o[dt][0] *= a0; o[dt][1] *= a0;
                o[dt][2] *= a1; o[dt][3] *= a1;
            }
        }

        if (kt + 1 < nk) cp_wait<1>(); else cp_wait<0>();
        __syncthreads();

        if (!skip) {
            const float* Vsm = sm + ((kt & 1) ? VOFF1 : VOFF0);
#pragma unroll
            for (int kc = 0; kc < 8; kc++) {
                uint32_t af[4];
                const float* pr = Ps + g4*68 + kc*8 + c4;
                af[0] = __float_as_uint(pr[0]);
                af[1] = __float_as_uint(pr[8*68]);
                af[2] = __float_as_uint(pr[4]);
                af[3] = __float_as_uint(pr[8*68 + 4]);
#pragma unroll
                for (int dt = 0; dt < 16; dt++) {
                    const float* vp = Vsm + (kc*8 + c4)*136 + dt*8 + g4;
                    mma_tf32(o[dt], af,
                             __float_as_uint(vp[0]), __float_as_uint(vp[4*136]));
                }
            }
        }

        if (kt + 1 < nk) {
            const size_t kvoff = ((size_t)(b*T_ + kc0 + 64)*HKV_ + kvh)*DH_;
            const uint32_t vb = sbase + (uint32_t)(((kt+1)&1) ? VOFF1 : VOFF0)*4;
#pragma unroll
            for (int i = 0; i < 8; i++) {
                const int idx = tid + i*256, row = idx >> 5, cc = (idx & 31)*4;
                cp_async16(vb + (uint32_t)(row*136 + cc)*4,
                           Vg + kvoff + (size_t)row*NKV_ + cc);
            }
            cp_commit();
        }
    }

    const float inv0 = 1.f / l0, inv1 = 1.f / l1;
    const size_t base0 = ((size_t)(b*T_ + qrow0 + g4))*NQ_ + h*DH_ + 2*c4;
    const size_t base1 = base0 + (size_t)8*NQ_;
#pragma unroll
    for (int dt = 0; dt < 16; dt++) {
        float v0 = o[dt][0]*inv0, v1 = o[dt][1]*inv0;
        float v2 = o[dt][2]*inv1, v3 = o[dt][3]*inv1;
        __nv_bfloat162 h0, h1, lo0, lo1;
        h0.x = __float2bfloat16(v0); h0.y = __float2bfloat16(v1);
        h1.x = __float2bfloat16(v2); h1.y = __float2bfloat16(v3);
        lo0.x = __float2bfloat16(v0 - __bfloat162float(h0.x));
        lo0.y = __float2bfloat16(v1 - __bfloat162float(h0.y));
        lo1.x = __float2bfloat16(v2 - __bfloat162float(h1.x));
        lo1.y = __float2bfloat16(v3 - __bfloat162float(h1.y));
        *(__nv_bfloat162*)(Ahi + base0 + dt*8) = h0;
        *(__nv_bfloat162*)(Ahi + base1 + dt*8) = h1;
        *(__nv_bfloat162*)(Alo + base0 + dt*8) = lo0;
        *(__nv_bfloat162*)(Alo + base1 + dt*8) = lo1;
    }
}

// ---------------------------------------------------------------------------
extern "C" void kernel_launch(void* const* d_in, const int* in_sizes, int n_in,
                              void* d_out, int out_size)
{
    const float* x    = (const float*)d_in[0];
    const float* cosb = (const float*)d_in[1];
    const float* sinb = (const float*)d_in[2];
    const float* Wq   = (const float*)d_in[3];
    const float* Wk   = (const float*)d_in[4];
    const float* Wv   = (const float*)d_in[5];
    const float* Wo   = (const float*)d_in[6];
    const float* temp = (const float*)d_in[7];
    float* out = (float*)d_out;

    float *q, *k, *v;
    cudaGetSymbolAddress((void**)&q, g_q);
    cudaGetSymbolAddress((void**)&k, g_k);
    cudaGetSymbolAddress((void**)&v, g_v);

    __nv_bfloat16 *xhi, *xlo, *qwhi, *qwlo, *kwhi, *kwlo, *vwhi, *vwlo,
                  *owhi, *owlo, *ahi, *alo;
    cudaGetSymbolAddress((void**)&xhi,  g_xhi);
    cudaGetSymbolAddress((void**)&xlo,  g_xlo);
    cudaGetSymbolAddress((void**)&qwhi, g_qwhi);
    cudaGetSymbolAddress((void**)&qwlo, g_qwlo);
    cudaGetSymbolAddress((void**)&kwhi, g_kwhi);
    cudaGetSymbolAddress((void**)&kwlo, g_kwlo);
    cudaGetSymbolAddress((void**)&vwhi, g_vwhi);
    cudaGetSymbolAddress((void**)&vwlo, g_vwlo);
    cudaGetSymbolAddress((void**)&owhi, g_owhi);
    cudaGetSymbolAddress((void**)&owlo, g_owlo);
    cudaGetSymbolAddress((void**)&ahi,  g_ahi);
    cudaGetSymbolAddress((void**)&alo,  g_alo);

    cudaFuncSetAttribute(gemm_bf16x3,
                         cudaFuncAttributeMaxDynamicSharedMemorySize, GEMM_SMEM);
    cudaFuncSetAttribute(attn_tc,
                         cudaFuncAttributeMaxDynamicSharedMemorySize, ATTN_SMEM_B);

    split_kernel<<<(M_*D_ + 255)/256,   256>>>(x,  xhi,  xlo,  M_*D_);
    split_kernel<<<(NQ_*D_ + 255)/256,  256>>>(Wq, qwhi, qwlo, NQ_*D_);
    split_kernel<<<(NKV_*D_ + 255)/256, 256>>>(Wk, kwhi, kwlo, NKV_*D_);
    split_kernel<<<(NKV_*D_ + 255)/256, 256>>>(Wv, vwhi, vwlo, NKV_*D_);
    split_kernel<<<(D_*D_ + 255)/256,   256>>>(Wo, owhi, owlo, D_*D_);

    gemm_bf16x3<<<dim3(NQ_/128,  M_/128), 256, GEMM_SMEM>>>(xhi, xlo, qwhi, qwlo, q, M_, NQ_,  D_);
    gemm_bf16x3<<<dim3(NKV_/128, M_/128), 256, GEMM_SMEM>>>(xhi, xlo, kwhi, kwlo, k, M_, NKV_, D_);
    gemm_bf16x3<<<dim3(NKV_/128, M_/128), 256, GEMM_SMEM>>>(xhi, xlo, vwhi, vwlo, v, M_, NKV_, D_);

    rope_tf32<<<M_, 256>>>(q, k, v, cosb, sinb, temp);

    attn_tc<<<dim3(16, H_, B_), 256, ATTN_SMEM_B>>>(q, k, v, ahi, alo);

    gemm_bf16x3<<<dim3(D_/128, M_/128), 256, GEMM_SMEM>>>(ahi, alo, owhi, owlo, out, M_, D_, D_);
}

// round 11
// speedup vs baseline: 1.5617x; 1.5617x over previous
#include <cuda_runtime.h>
#include <cuda_bf16.h>
#include <cstdint>

// Problem constants
#define B_  2
#define T_  2048
#define D_  2048
#define H_  16
#define HKV_ 4
#define DH_ 128
#define M_  (B_*T_)
#define NQ_ (H_*DH_)
#define NKV_ (HKV_*DH_)

// fp32 scratch
__device__ float g_q[(size_t)M_ * NQ_];
__device__ float g_k[(size_t)M_ * NKV_];
__device__ float g_v[(size_t)M_ * NKV_];

// bf16 split scratch
__device__ __nv_bfloat16 g_xhi[(size_t)M_ * D_],  g_xlo[(size_t)M_ * D_];
__device__ __nv_bfloat16 g_qwhi[(size_t)NQ_ * D_], g_qwlo[(size_t)NQ_ * D_];
__device__ __nv_bfloat16 g_kwhi[(size_t)NKV_ * D_], g_kwlo[(size_t)NKV_ * D_];
__device__ __nv_bfloat16 g_vwhi[(size_t)NKV_ * D_], g_vwlo[(size_t)NKV_ * D_];
__device__ __nv_bfloat16 g_owhi[(size_t)D_ * D_],  g_owlo[(size_t)D_ * D_];
__device__ __nv_bfloat16 g_ahi[(size_t)M_ * NQ_],  g_alo[(size_t)M_ * NQ_];

// ---------------------------------------------------------------------------
// PTX helpers (compute_103-safe: cp.async, ldmatrix, mma.sync only)
// ---------------------------------------------------------------------------
__device__ __forceinline__ void cp_async16(uint32_t s, const void* g) {
    asm volatile("cp.async.cg.shared.global [%0], [%1], 16;\n" :: "r"(s), "l"(g));
}
__device__ __forceinline__ void cp_commit() {
    asm volatile("cp.async.commit_group;\n");
}
template<int N> __device__ __forceinline__ void cp_wait() {
    asm volatile("cp.async.wait_group %0;\n" :: "n"(N));
}
__device__ __forceinline__ void ldsm_x4(uint32_t& r0, uint32_t& r1,
                                        uint32_t& r2, uint32_t& r3, uint32_t a) {
    asm volatile("ldmatrix.sync.aligned.m8n8.x4.shared.b16 {%0,%1,%2,%3}, [%4];\n"
                 : "=r"(r0), "=r"(r1), "=r"(r2), "=r"(r3) : "r"(a));
}
__device__ __forceinline__ void mma_bf16(float* d, const uint32_t* a,
                                         uint32_t b0, uint32_t b1) {
    asm volatile(
        "mma.sync.aligned.m16n8k16.row.col.f32.bf16.bf16.f32 "
        "{%0,%1,%2,%3},{%4,%5,%6,%7},{%8,%9},{%0,%1,%2,%3};\n"
        : "+f"(d[0]), "+f"(d[1]), "+f"(d[2]), "+f"(d[3])
        : "r"(a[0]), "r"(a[1]), "r"(a[2]), "r"(a[3]), "r"(b0), "r"(b1));
}
__device__ __forceinline__ void mma_tf32(float* d, const uint32_t* a,
                                         uint32_t b0, uint32_t b1) {
    asm volatile(
        "mma.sync.aligned.m16n8k8.row.col.f32.tf32.tf32.f32 "
        "{%0,%1,%2,%3},{%4,%5,%6,%7},{%8,%9},{%0,%1,%2,%3};\n"
        : "+f"(d[0]), "+f"(d[1]), "+f"(d[2]), "+f"(d[3])
        : "r"(a[0]), "r"(a[1]), "r"(a[2]), "r"(a[3]), "r"(b0), "r"(b1));
}
__device__ __forceinline__ uint32_t f2tf32(float x) {
    uint32_t r;
    asm("cvt.rna.tf32.f32 %0, %1;" : "=r"(r) : "f"(x));
    return r;
}
__device__ __forceinline__ float tf32r(float x) { return __uint_as_float(f2tf32(x)); }
__device__ __forceinline__ float fexp2(float x) {
    float y;
    asm("ex2.approx.ftz.f32 %0, %1;" : "=f"(y) : "f"(x));
    return y;
}

// ---------------------------------------------------------------------------
// Split fp32 -> bf16 hi + lo
// ---------------------------------------------------------------------------
__global__ __launch_bounds__(256) void split_kernel(
    const float* __restrict__ in, __nv_bfloat16* __restrict__ hi,
    __nv_bfloat16* __restrict__ lo, int n)
{
    int i = blockIdx.x * blockDim.x + threadIdx.x;
    if (i < n) {
        float v = in[i];
        __nv_bfloat16 h = __float2bfloat16(v);
        hi[i] = h;
        lo[i] = __float2bfloat16(v - __bfloat162float(h));
    }
}

// ---------------------------------------------------------------------------
// bf16x3 NT GEMM core: C[m,n] = sum_k A[m,k]*W[n,k]  (fp32 out)
//   C ~= Ahi*Whi + Ahi*Wlo + Alo*Whi
// 128x128 tile, BK=64, 256 threads (8 warps, 2x4), warp tile 64x32,
// 2-stage cp.async, 144B smem row stride (conflict-free ldmatrix),
// pass-ordered MMA (16 independent accs between reuse).
// ---------------------------------------------------------------------------
#define BK_G    64
#define LDSR    72                     // bf16 elems per smem row (144 B)
#define TILE_B  (128*LDSR*2)           // 18432 B per matrix tile
#define STAGE_B (4*TILE_B)             // 73728 B
#define GEMM_SMEM (2*STAGE_B)          // 147456 B

__device__ __forceinline__ void gemm_load_stage(
    uint32_t sa, const __nv_bfloat16* Ahi, const __nv_bfloat16* Alo,
    const __nv_bfloat16* Whi, const __nv_bfloat16* Wlo,
    int bm, int bn, int K, int k0, int tid)
{
#pragma unroll
    for (int t = 0; t < 16; t++) {
        const int idx = tid + t * 256;     // 0..4095
        const int mat = idx >> 10;         // 0:Ahi 1:Alo 2:Whi 3:Wlo
        const int rem = idx & 1023;
        const int row = rem >> 3;          // 0..127
        const int c8  = (rem & 7) << 3;    // 0..56 (bf16 cols, 16B chunks)
        const size_t ga = (size_t)(bm + row) * K + k0 + c8;
        const size_t gw = (size_t)(bn + row) * K + k0 + c8;
        const uint32_t so = (uint32_t)(mat * TILE_B) + (uint32_t)(row * LDSR + c8) * 2;
        const __nv_bfloat16* g =
            (mat == 0) ? Ahi + ga : (mat == 1) ? Alo + ga :
            (mat == 2) ? Whi + gw : Wlo + gw;
        cp_async16(sa + so, g);
    }
}

__device__ __forceinline__ void gemm_core(
    __nv_bfloat16* smg,
    const __nv_bfloat16* __restrict__ Ahi, const __nv_bfloat16* __restrict__ Alo,
    const __nv_bfloat16* __restrict__ Whi, const __nv_bfloat16* __restrict__ Wlo,
    float* __restrict__ C, int N, int K, int bm, int bn)
{
    const int tid  = threadIdx.x;
    const int warp = tid >> 5, lane = tid & 31;
    const int wm = (warp >> 2) * 64;
    const int wn = (warp & 3) * 32;
    const uint32_t sbase = (uint32_t)__cvta_generic_to_shared(smg);

    float acc[4][4][4];
#pragma unroll
    for (int i = 0; i < 4; i++)
#pragma unroll
        for (int j = 0; j < 4; j++)
#pragma unroll
            for (int r = 0; r < 4; r++) acc[i][j][r] = 0.f;

    const int arow = (lane & 7) + ((lane >> 3) & 1) * 8;
    const int acb  = ((lane >> 4) & 1) * 16;
    const int brow = (lane & 7) + ((lane >> 4) & 1) * 8;
    const int bcb  = ((lane >> 3) & 1) * 16;

    gemm_load_stage(sbase, Ahi, Alo, Whi, Wlo, bm, bn, K, 0, tid);
    cp_commit();

    const int NC = K / BK_G;
    for (int c = 0; c < NC; c++) {
        if (c + 1 < NC) {
            gemm_load_stage(sbase + ((c + 1) & 1) * STAGE_B,
                            Ahi, Alo, Whi, Wlo, bm, bn, K, (c + 1) * BK_G, tid);
            cp_commit();
            cp_wait<1>();
        } else {
            cp_wait<0>();
        }
        __syncthreads();

        const uint32_t base = sbase + (c & 1) * STAGE_B;
        const uint32_t aAhi = base;
        const uint32_t aAlo = base + TILE_B;
        const uint32_t aWhi = base + 2*TILE_B;
        const uint32_t aWlo = base + 3*TILE_B;

#pragma unroll
        for (int kh = 0; kh < 4; kh++) {
            const int kb = kh * 32;    // 16 bf16 cols per k-half
            uint32_t bhi[4][2], blo[4][2];
#pragma unroll
            for (int jj = 0; jj < 2; jj++) {
                uint32_t ad = aWhi + (uint32_t)((wn + jj*16 + brow) * LDSR) * 2 + bcb + kb;
                ldsm_x4(bhi[2*jj][0], bhi[2*jj][1], bhi[2*jj+1][0], bhi[2*jj+1][1], ad);
                ad = aWlo + (uint32_t)((wn + jj*16 + brow) * LDSR) * 2 + bcb + kb;
                ldsm_x4(blo[2*jj][0], blo[2*jj][1], blo[2*jj+1][0], blo[2*jj+1][1], ad);
            }
            uint32_t ah[4][4], al[4][4];
#pragma unroll
            for (int i = 0; i < 4; i++) {
                uint32_t ad = aAhi + (uint32_t)((wm + i*16 + arow) * LDSR) * 2 + acb + kb;
                ldsm_x4(ah[i][0], ah[i][1], ah[i][2], ah[i][3], ad);
                ad = aAlo + (uint32_t)((wm + i*16 + arow) * LDSR) * 2 + acb + kb;
                ldsm_x4(al[i][0], al[i][1], al[i][2], al[i][3], ad);
            }
            // pass 1: Ahi * Whi  (16 independent accumulators)
#pragma unroll
            for (int i = 0; i < 4; i++)
#pragma unroll
                for (int j = 0; j < 4; j++)
                    mma_bf16(acc[i][j], ah[i], bhi[j][0], bhi[j][1]);
            // pass 2: Ahi * Wlo
#pragma unroll
            for (int i = 0; i < 4; i++)
#pragma unroll
                for (int j = 0; j < 4; j++)
                    mma_bf16(acc[i][j], ah[i], blo[j][0], blo[j][1]);
            // pass 3: Alo * Whi
#pragma unroll
            for (int i = 0; i < 4; i++)
#pragma unroll
                for (int j = 0; j < 4; j++)
                    mma_bf16(acc[i][j], al[i], bhi[j][0], bhi[j][1]);
        }
        __syncthreads();
    }

    const int er = lane >> 2, ec = (lane & 3) * 2;
#pragma unroll
    for (int i = 0; i < 4; i++)
#pragma unroll
        for (int j = 0; j < 4; j++) {
            float* p0 = C + (size_t)(bm + wm + 16*i + er) * N + bn + wn + 8*j + ec;
            float* p1 = p0 + (size_t)8 * N;
            *(float2*)p0 = make_float2(acc[i][j][0], acc[i][j][1]);
            *(float2*)p1 = make_float2(acc[i][j][2], acc[i][j][3]);
        }
}

// Fused QKV projection: grid (24, 32). bx<16 -> Q, 16..19 -> K, 20..23 -> V.
__global__ __launch_bounds__(256) void gemm_qkv(
    const __nv_bfloat16* __restrict__ xhi, const __nv_bfloat16* __restrict__ xlo,
    const __nv_bfloat16* __restrict__ qwhi, const __nv_bfloat16* __restrict__ qwlo,
    const __nv_bfloat16* __restrict__ kwhi, const __nv_bfloat16* __restrict__ kwlo,
    const __nv_bfloat16* __restrict__ vwhi, const __nv_bfloat16* __restrict__ vwlo,
    float* __restrict__ q, float* __restrict__ k, float* __restrict__ v)
{
    extern __shared__ __nv_bfloat16 smg[];
    const int bx = blockIdx.x;
    const __nv_bfloat16 *Whi, *Wlo;
    float* C;
    int N, bn;
    if (bx < 16)      { Whi = qwhi; Wlo = qwlo; C = q; N = NQ_;  bn = bx * 128; }
    else if (bx < 20) { Whi = kwhi; Wlo = kwlo; C = k; N = NKV_; bn = (bx - 16) * 128; }
    else              { Whi = vwhi; Wlo = vwlo; C = v; N = NKV_; bn = (bx - 20) * 128; }
    gemm_core(smg, xhi, xlo, Whi, Wlo, C, N, D_, blockIdx.y * 128, bn);
}

// Generic GEMM (used for Wo)
__global__ __launch_bounds__(256) void gemm_nt(
    const __nv_bfloat16* __restrict__ Ahi, const __nv_bfloat16* __restrict__ Alo,
    const __nv_bfloat16* __restrict__ Whi, const __nv_bfloat16* __restrict__ Wlo,
    float* __restrict__ C, int N, int K)
{
    extern __shared__ __nv_bfloat16 smg[];
    gemm_core(smg, Ahi, Alo, Whi, Wlo, C, N, K, blockIdx.y * 128, blockIdx.x * 128);
}

// ---------------------------------------------------------------------------
// RoPE + scale fold + round-to-TF32 in place on q, k, v.
// ---------------------------------------------------------------------------
__global__ __launch_bounds__(256) void rope_tf32(
    float* __restrict__ q, float* __restrict__ k, float* __restrict__ v,
    const float* __restrict__ cosb, const float* __restrict__ sinb,
    const float* __restrict__ temp)
{
    const int token = blockIdx.x;
    const int t = token & (T_ - 1);
    const float SC = 0.08838834764831845f * 1.4426950408889634f;
    for (int s = threadIdx.x; s < 1536; s += blockDim.x) {
        const int head = s >> 6;
        const int i = s & 63;
        float* base;
        float scale = 1.0f;
        bool dorope = true;
        if (head < 16) {
            base = q + ((size_t)token * H_ + head) * DH_;
            scale = temp[head] * SC;
        } else if (head < 20) {
            base = k + ((size_t)token * HKV_ + (head - 16)) * DH_;
        } else {
            base = v + ((size_t)token * HKV_ + (head - 20)) * DH_;
            dorope = false;
        }
        if (dorope && i < 32) {
            const float c  = cosb[t*32 + i];
            const float sn = sinb[t*32 + i];
            const float x1 = base[2*i];
            const float x2 = base[2*i + 1];
            base[2*i]     = tf32r((x1*c - x2*sn) * scale);
            base[2*i + 1] = tf32r((x1*sn + x2*c) * scale);
        } else {
            const int d = dorope ? 64 + (i - 32) * 2 : i * 2;
            base[d]     = tf32r(base[d] * scale);
            base[d + 1] = tf32r(base[d + 1] * scale);
        }
    }
}

// ---------------------------------------------------------------------------
// TF32 tensor-core causal GQA flash attention (proven round-8 kernel).
// ---------------------------------------------------------------------------
#define KOFF0 0
#define KOFF1 8448
#define VOFF0 16896
#define VOFF1 25600
#define POFF  34304
#define ATTN_SMEM_B ((POFF + 8704) * 4)

__global__ __launch_bounds__(256, 1) void attn_tc(
    const float* __restrict__ Qg, const float* __restrict__ Kg,
    const float* __restrict__ Vg,
    __nv_bfloat16* __restrict__ Ahi, __nv_bfloat16* __restrict__ Alo)
{
    extern __shared__ float sm[];
    const uint32_t sbase = (uint32_t)__cvta_generic_to_shared(sm);
    const int qt = 15 - blockIdx.x;
    const int h = blockIdx.y, b = blockIdx.z;
    const int kvh = h >> 2;
    const int tid = threadIdx.x;
    const int warp = tid >> 5, lane = tid & 31;
    const int g4 = lane >> 2, c4 = lane & 3;
    const int qrow0 = qt * 128 + warp * 16;
    const int nk = 2 * qt + 2;

    uint32_t qf[16][4];
    {
        const float* Q0 = Qg + ((size_t)(b*T_ + qrow0 + g4)*H_ + h)*DH_;
        const float* Q1 = Q0 + (size_t)8*H_*DH_;
#pragma unroll
        for (int kc = 0; kc < 16; kc++) {
            const int c0 = kc*8 + c4;
            qf[kc][0] = __float_as_uint(__ldg(Q0 + c0));
            qf[kc][1] = __float_as_uint(__ldg(Q1 + c0));
            qf[kc][2] = __float_as_uint(__ldg(Q0 + c0 + 4));
            qf[kc][3] = __float_as_uint(__ldg(Q1 + c0 + 4));
        }
    }

    float o[16][4];
#pragma unroll
    for (int dt = 0; dt < 16; dt++)
#pragma unroll
        for (int r = 0; r < 4; r++) o[dt][r] = 0.f;
    float m0 = -1e30f, m1 = -1e30f, l0 = 0.f, l1 = 0.f;

    float* Ps = sm + POFF + warp * 1088;

    {
        const size_t kvoff = ((size_t)(b*T_)*HKV_ + kvh)*DH_;
#pragma unroll
        for (int i = 0; i < 8; i++) {
            const int idx = tid + i*256, row = idx >> 5, cc = (idx & 31)*4;
            cp_async16(sbase + (uint32_t)(KOFF0 + row*132 + cc)*4,
                       Kg + kvoff + (size_t)row*NKV_ + cc);
        }
        cp_commit();
#pragma unroll
        for (int i = 0; i < 8; i++) {
            const int idx = tid + i*256, row = idx >> 5, cc = (idx & 31)*4;
            cp_async16(sbase + (uint32_t)(VOFF0 + row*136 + cc)*4,
                       Vg + kvoff + (size_t)row*NKV_ + cc);
        }
        cp_commit();
    }

    for (int kt = 0; kt < nk; kt++) {
        const int kc0 = kt * 64;
        const bool skip = (kc0 > qrow0 + 15);
        cp_wait<1>();
        __syncthreads();

        float sacc[8][4];
        if (!skip) {
#pragma unroll
            for (int nt = 0; nt < 8; nt++)
#pragma unroll
                for (int r = 0; r < 4; r++) sacc[nt][r] = 0.f;
            const float* Ksm = sm + ((kt & 1) ? KOFF1 : KOFF0);
#pragma unroll
            for (int kc = 0; kc < 16; kc++) {
                const int dk = kc*8 + c4;
#pragma unroll
                for (int nt = 0; nt < 8; nt++) {
                    const float* kp = Ksm + (nt*8 + g4)*132 + dk;
                    mma_tf32(sacc[nt], qf[kc],
                             __float_as_uint(kp[0]), __float_as_uint(kp[4]));
                }
            }
        }

        if (kt + 1 < nk) {
            const size_t kvoff = ((size_t)(b*T_ + kc0 + 64)*HKV_ + kvh)*DH_;
            const uint32_t kb = sbase + (uint32_t)(((kt+1)&1) ? KOFF1 : KOFF0)*4;
#pragma unroll
            for (int i = 0; i < 8; i++) {
                const int idx = tid + i*256, row = idx >> 5, cc = (idx & 31)*4;
                cp_async16(kb + (uint32_t)(row*132 + cc)*4,
                           Kg + kvoff + (size_t)row*NKV_ + cc);
            }
            cp_commit();
        }

        if (!skip) {
            if (kc0 + 63 > qrow0) {
#pragma unroll
                for (int nt = 0; nt < 8; nt++) {
                    const int cc = kc0 + nt*8 + 2*c4;
                    const int r0 = qrow0 + g4, r1 = r0 + 8;
                    if (cc     > r0) sacc[nt][0] = -1e30f;
                    if (cc + 1 > r0) sacc[nt][1] = -1e30f;
                    if (cc     > r1) sacc[nt][2] = -1e30f;
                    if (cc + 1 > r1) sacc[nt][3] = -1e30f;
                }
            }
            float rm0 = -1e30f, rm1 = -1e30f;
#pragma unroll
            for (int nt = 0; nt < 8; nt++) {
                rm0 = fmaxf(rm0, fmaxf(sacc[nt][0], sacc[nt][1]));
                rm1 = fmaxf(rm1, fmaxf(sacc[nt][2], sacc[nt][3]));
            }
#pragma unroll
            for (int off = 1; off <= 2; off <<= 1) {
                rm0 = fmaxf(rm0, __shfl_xor_sync(0xffffffffu, rm0, off));
                rm1 = fmaxf(rm1, __shfl_xor_sync(0xffffffffu, rm1, off));
            }
            const float mn0 = fmaxf(m0, rm0), mn1 = fmaxf(m1, rm1);
            const float a0 = fexp2(m0 - mn0), a1 = fexp2(m1 - mn1);
            m0 = mn0; m1 = mn1;
            float rs0 = 0.f, rs1 = 0.f;
#pragma unroll
            for (int nt = 0; nt < 8; nt++) {
                float p0 = fexp2(sacc[nt][0] - mn0);
                float p1 = fexp2(sacc[nt][1] - mn0);
                float p2 = fexp2(sacc[nt][2] - mn1);
                float p3 = fexp2(sacc[nt][3] - mn1);
                rs0 += p0 + p1; rs1 += p2 + p3;
                float* pr = Ps + g4*68 + nt*8 + 2*c4;
                *(float2*)pr = make_float2(__uint_as_float(f2tf32(p0)),
                                           __uint_as_float(f2tf32(p1)));
                *(float2*)(pr + 8*68) = make_float2(__uint_as_float(f2tf32(p2)),
                                                    __uint_as_float(f2tf32(p3)));
            }
#pragma unroll
            for (int off = 1; off <= 2; off <<= 1) {
                rs0 += __shfl_xor_sync(0xffffffffu, rs0, off);
                rs1 += __shfl_xor_sync(0xffffffffu, rs1, off);
            }
            l0 = l0 * a0 + rs0;
            l1 = l1 * a1 + rs1;
#pragma unroll
            for (int dt = 0; dt < 16; dt++) {
                o[dt][0] *= a0; o[dt][1] *= a0;
                o[dt][2] *= a1; o[dt][3] *= a1;
            }
        }

        if (kt + 1 < nk) cp_wait<1>(); else cp_wait<0>();
        __syncthreads();

        if (!skip) {
            const float* Vsm = sm + ((kt & 1) ? VOFF1 : VOFF0);
#pragma unroll
            for (int kc = 0; kc < 8; kc++) {
                uint32_t af[4];
                const float* pr = Ps + g4*68 + kc*8 + c4;
                af[0] = __float_as_uint(pr[0]);
                af[1] = __float_as_uint(pr[8*68]);
                af[2] = __float_as_uint(pr[4]);
                af[3] = __float_as_uint(pr[8*68 + 4]);
#pragma unroll
                for (int dt = 0; dt < 16; dt++) {
                    const float* vp = Vsm + (kc*8 + c4)*136 + dt*8 + g4;
                    mma_tf32(o[dt], af,
                             __float_as_uint(vp[0]), __float_as_uint(vp[4*136]));
                }
            }
        }

        if (kt + 1 < nk) {
            const size_t kvoff = ((size_t)(b*T_ + kc0 + 64)*HKV_ + kvh)*DH_;
            const uint32_t vb = sbase + (uint32_t)(((kt+1)&1) ? VOFF1 : VOFF0)*4;
#pragma unroll
            for (int i = 0; i < 8; i++) {
                const int idx = tid + i*256, row = idx >> 5, cc = (idx & 31)*4;
                cp_async16(vb + (uint32_t)(row*136 + cc)*4,
                           Vg + kvoff + (size_t)row*NKV_ + cc);
            }
            cp_commit();
        }
    }

    const float inv0 = 1.f / l0, inv1 = 1.f / l1;
    const size_t base0 = ((size_t)(b*T_ + qrow0 + g4))*NQ_ + h*DH_ + 2*c4;
    const size_t base1 = base0 + (size_t)8*NQ_;
#pragma unroll
    for (int dt = 0; dt < 16; dt++) {
        float v0 = o[dt][0]*inv0, v1 = o[dt][1]*inv0;
        float v2 = o[dt][2]*inv1, v3 = o[dt][3]*inv1;
        __nv_bfloat162 h0, h1, lo0, lo1;
        h0.x = __float2bfloat16(v0); h0.y = __float2bfloat16(v1);
        h1.x = __float2bfloat16(v2); h1.y = __float2bfloat16(v3);
        lo0.x = __float2bfloat16(v0 - __bfloat162float(h0.x));
        lo0.y = __float2bfloat16(v1 - __bfloat162float(h0.y));
        lo1.x = __float2bfloat16(v2 - __bfloat162float(h1.x));
        lo1.y = __float2bfloat16(v3 - __bfloat162float(h1.y));
        *(__nv_bfloat162*)(Ahi + base0 + dt*8) = h0;
        *(__nv_bfloat162*)(Ahi + base1 + dt*8) = h1;
        *(__nv_bfloat162*)(Alo + base0 + dt*8) = lo0;
        *(__nv_bfloat162*)(Alo + base1 + dt*8) = lo1;
    }
}

// ---------------------------------------------------------------------------
extern "C" void kernel_launch(void* const* d_in, const int* in_sizes, int n_in,
                              void* d_out, int out_size)
{
    const float* x    = (const float*)d_in[0];
    const float* cosb = (const float*)d_in[1];
    const float* sinb = (const float*)d_in[2];
    const float* Wq   = (const float*)d_in[3];
    const float* Wk   = (const float*)d_in[4];
    const float* Wv   = (const float*)d_in[5];
    const float* Wo   = (const float*)d_in[6];
    const float* temp = (const float*)d_in[7];
    float* out = (float*)d_out;

    float *q, *k, *v;
    cudaGetSymbolAddress((void**)&q, g_q);
    cudaGetSymbolAddress((void**)&k, g_k);
    cudaGetSymbolAddress((void**)&v, g_v);

    __nv_bfloat16 *xhi, *xlo, *qwhi, *qwlo, *kwhi, *kwlo, *vwhi, *vwlo,
                  *owhi, *owlo, *ahi, *alo;
    cudaGetSymbolAddress((void**)&xhi,  g_xhi);
    cudaGetSymbolAddress((void**)&xlo,  g_xlo);
    cudaGetSymbolAddress((void**)&qwhi, g_qwhi);
    cudaGetSymbolAddress((void**)&qwlo, g_qwlo);
    cudaGetSymbolAddress((void**)&kwhi, g_kwhi);
    cudaGetSymbolAddress((void**)&kwlo, g_kwlo);
    cudaGetSymbolAddress((void**)&vwhi, g_vwhi);
    cudaGetSymbolAddress((void**)&vwlo, g_vwlo);
    cudaGetSymbolAddress((void**)&owhi, g_owhi);
    cudaGetSymbolAddress((void**)&owlo, g_owlo);
    cudaGetSymbolAddress((void**)&ahi,  g_ahi);
    cudaGetSymbolAddress((void**)&alo,  g_alo);

    cudaFuncSetAttribute(gemm_qkv,
                         cudaFuncAttributeMaxDynamicSharedMemorySize, GEMM_SMEM);
    cudaFuncSetAttribute(gemm_nt,
                         cudaFuncAttributeMaxDynamicSharedMemorySize, GEMM_SMEM);
    cudaFuncSetAttribute(attn_tc,
                         cudaFuncAttributeMaxDynamicSharedMemorySize, ATTN_SMEM_B);

    split_kernel<<<(M_*D_ + 255)/256,   256>>>(x,  xhi,  xlo,  M_*D_);
    split_kernel<<<(NQ_*D_ + 255)/256,  256>>>(Wq, qwhi, qwlo, NQ_*D_);
    split_kernel<<<(NKV_*D_ + 255)/256, 256>>>(Wk, kwhi, kwlo, NKV_*D_);
    split_kernel<<<(NKV_*D_ + 255)/256, 256>>>(Wv, vwhi, vwlo, NKV_*D_);
    split_kernel<<<(D_*D_ + 255)/256,   256>>>(Wo, owhi, owlo, D_*D_);

    gemm_qkv<<<dim3(24, M_/128), 256, GEMM_SMEM>>>(
        xhi, xlo, qwhi, qwlo, kwhi, kwlo, vwhi, vwlo, q, k, v);

    rope_tf32<<<M_, 256>>>(q, k, v, cosb, sinb, temp);

    attn_tc<<<dim3(16, H_, B_), 256, ATTN_SMEM_B>>>(q, k, v, ahi, alo);

    gemm_nt<<<dim3(D_/128, M_/128), 256, GEMM_SMEM>>>(ahi, alo, owhi, owlo, out, D_, D_);
}

// round 13
// speedup vs baseline: 1.8178x; 1.1640x over previous
#include <cuda_runtime.h>
#include <cuda_bf16.h>
#include <cstdint>

// Problem constants
#define B_  2
#define T_  2048
#define D_  2048
#define H_  16
#define HKV_ 4
#define DH_ 128
#define M_  (B_*T_)
#define NQ_ (H_*DH_)
#define NKV_ (HKV_*DH_)

// fp32 scratch
__device__ float g_q[(size_t)M_ * NQ_];
__device__ float g_k[(size_t)M_ * NKV_];
__device__ float g_v[(size_t)M_ * NKV_];
__device__ float g_att[(size_t)M_ * NQ_];
// tf32-rounded fp32 operands
__device__ float g_x32[(size_t)M_ * D_];
__device__ float g_wq32[(size_t)NQ_ * D_];
__device__ float g_wk32[(size_t)NKV_ * D_];
__device__ float g_wv32[(size_t)NKV_ * D_];
__device__ float g_wo32[(size_t)D_ * D_];

// ---------------------------------------------------------------------------
// PTX helpers (compute_103-safe)
// ---------------------------------------------------------------------------
__device__ __forceinline__ void cp_async16(uint32_t s, const void* g) {
    asm volatile("cp.async.cg.shared.global [%0], [%1], 16;\n" :: "r"(s), "l"(g));
}
__device__ __forceinline__ void cp_commit() {
    asm volatile("cp.async.commit_group;\n");
}
template<int N> __device__ __forceinline__ void cp_wait() {
    asm volatile("cp.async.wait_group %0;\n" :: "n"(N));
}
__device__ __forceinline__ void ldsm_x4(uint32_t& r0, uint32_t& r1,
                                        uint32_t& r2, uint32_t& r3, uint32_t a) {
    asm volatile("ldmatrix.sync.aligned.m8n8.x4.shared.b16 {%0,%1,%2,%3}, [%4];\n"
                 : "=r"(r0), "=r"(r1), "=r"(r2), "=r"(r3) : "r"(a));
}
__device__ __forceinline__ void mma_tf32(float* d, const uint32_t* a,
                                         uint32_t b0, uint32_t b1) {
    asm volatile(
        "mma.sync.aligned.m16n8k8.row.col.f32.tf32.tf32.f32 "
        "{%0,%1,%2,%3},{%4,%5,%6,%7},{%8,%9},{%0,%1,%2,%3};\n"
        : "+f"(d[0]), "+f"(d[1]), "+f"(d[2]), "+f"(d[3])
        : "r"(a[0]), "r"(a[1]), "r"(a[2]), "r"(a[3]), "r"(b0), "r"(b1));
}
__device__ __forceinline__ uint32_t f2tf32(float x) {
    uint32_t r;
    asm("cvt.rna.tf32.f32 %0, %1;" : "=r"(r) : "f"(x));
    return r;
}
__device__ __forceinline__ float tf32r(float x) { return __uint_as_float(f2tf32(x)); }
__device__ __forceinline__ float fexp2(float x) {
    float y;
    asm("ex2.approx.ftz.f32 %0, %1;" : "=f"(y) : "f"(x));
    return y;
}

// ---------------------------------------------------------------------------
// Round fp32 -> tf32-in-fp32
// ---------------------------------------------------------------------------
__global__ __launch_bounds__(256) void t32_kernel(
    const float* __restrict__ in, float* __restrict__ out, int n)
{
    int i = blockIdx.x * blockDim.x + threadIdx.x;
    if (i < n) out[i] = tf32r(in[i]);
}

// ---------------------------------------------------------------------------
// TF32 NT GEMM core: C[m,n] = sum_k A[m,k]*W[n,k]  (fp32 out, single pass)
// 128x128 tile, BK=64, 256 threads (8 warps, 2x4), warp tile 64x32,
// mma.m16n8k8.tf32, 2-stage cp.async, 272B smem row stride.
// ---------------------------------------------------------------------------
#define BK32    64
#define ROWB    272                    // 64 f32 + 16B pad
#define TILE32  (128*ROWB)             // 34816 B per matrix tile
#define STAGE32 (2*TILE32)             // 69632 B
#define GEMM32_SMEM (2*STAGE32)        // 139264 B

__device__ __forceinline__ void g32_load_stage(
    uint32_t sa, const float* __restrict__ A, const float* __restrict__ W,
    int bm, int bn, int K, int k0, int tid)
{
#pragma unroll
    for (int t = 0; t < 16; t++) {
        const int idx = tid + t * 256;      // 0..4095
        const int mat = idx >> 11;          // 0:A 1:W
        const int rem = idx & 2047;
        const int row = rem >> 4;           // 0..127
        const int c4  = (rem & 15) * 4;     // f32 col, 16B chunks
        const float* g = (mat == 0) ? A + (size_t)(bm + row) * K + k0 + c4
                                    : W + (size_t)(bn + row) * K + k0 + c4;
        cp_async16(sa + (uint32_t)(mat * TILE32) + (uint32_t)(row * ROWB + c4 * 4), g);
    }
}

__device__ __forceinline__ void g32_core(
    char* smg, const float* __restrict__ A, const float* __restrict__ W,
    float* __restrict__ C, int N, int K, int bm, int bn)
{
    const int tid  = threadIdx.x;
    const int warp = tid >> 5, lane = tid & 31;
    const int wm = (warp >> 2) * 64;
    const int wn = (warp & 3) * 32;
    const uint32_t sbase = (uint32_t)__cvta_generic_to_shared(smg);

    float acc[4][4][4];
#pragma unroll
    for (int i = 0; i < 4; i++)
#pragma unroll
        for (int j = 0; j < 4; j++)
#pragma unroll
            for (int r = 0; r < 4; r++) acc[i][j][r] = 0.f;

    // ldmatrix address components (same row/col split as proven bf16 kernel)
    const int arow = (lane & 7) + ((lane >> 3) & 1) * 8;   // A m-row within 16
    const int acb  = ((lane >> 4) & 1) * 16;               // A k byte offset
    const int brow = (lane & 7) + ((lane >> 4) & 1) * 8;   // B n-row within 16
    const int bcb  = ((lane >> 3) & 1) * 16;               // B k byte offset

    g32_load_stage(sbase, A, W, bm, bn, K, 0, tid);
    cp_commit();

    const int NC = K / BK32;
    for (int c = 0; c < NC; c++) {
        if (c + 1 < NC) {
            g32_load_stage(sbase + ((c + 1) & 1) * STAGE32,
                           A, W, bm, bn, K, (c + 1) * BK32, tid);
            cp_commit();
            cp_wait<1>();
        } else {
            cp_wait<0>();
        }
        __syncthreads();

        const uint32_t aA = sbase + (c & 1) * STAGE32;
        const uint32_t aW = aA + TILE32;

#pragma unroll
        for (int ks = 0; ks < 8; ks++) {
            const int kb = ks * 32;       // 8 f32 per k-step
            uint32_t b[4][2];
#pragma unroll
            for (int jj = 0; jj < 2; jj++) {
                const uint32_t ad = aW + (uint32_t)((wn + jj*16 + brow) * ROWB) + bcb + kb;
                ldsm_x4(b[2*jj][0], b[2*jj][1], b[2*jj+1][0], b[2*jj+1][1], ad);
            }
            uint32_t a[4][4];
#pragma unroll
            for (int i = 0; i < 4; i++) {
                const uint32_t ad = aA + (uint32_t)((wm + i*16 + arow) * ROWB) + acb + kb;
                ldsm_x4(a[i][0], a[i][1], a[i][2], a[i][3], ad);
            }
#pragma unroll
            for (int i = 0; i < 4; i++)
#pragma unroll
                for (int j = 0; j < 4; j++)
                    mma_tf32(acc[i][j], a[i], b[j][0], b[j][1]);
        }
        __syncthreads();
    }

    const int er = lane >> 2, ec = (lane & 3) * 2;
#pragma unroll
    for (int i = 0; i < 4; i++)
#pragma unroll
        for (int j = 0; j < 4; j++) {
            float* p0 = C + (size_t)(bm + wm + 16*i + er) * N + bn + wn + 8*j + ec;
            float* p1 = p0 + (size_t)8 * N;
            *(float2*)p0 = make_float2(acc[i][j][0], acc[i][j][1]);
            *(float2*)p1 = make_float2(acc[i][j][2], acc[i][j][3]);
        }
}

// Fused QKV projection: grid (24, 32). bx<16 -> Q, 16..19 -> K, 20..23 -> V.
__global__ __launch_bounds__(256) void gemm_qkv32(
    const float* __restrict__ x32,
    const float* __restrict__ wq32, const float* __restrict__ wk32,
    const float* __restrict__ wv32,
    float* __restrict__ q, float* __restrict__ k, float* __restrict__ v)
{
    extern __shared__ char smg[];
    const int bx = blockIdx.x;
    const float* W;
    float* C;
    int N, bn;
    if (bx < 16)      { W = wq32; C = q; N = NQ_;  bn = bx * 128; }
    else if (bx < 20) { W = wk32; C = k; N = NKV_; bn = (bx - 16) * 128; }
    else              { W = wv32; C = v; N = NKV_; bn = (bx - 20) * 128; }
    g32_core(smg, x32, W, C, N, D_, blockIdx.y * 128, bn);
}

// Generic tf32 GEMM (used for Wo)
__global__ __launch_bounds__(256) void gemm32_nt(
    const float* __restrict__ A, const float* __restrict__ W,
    float* __restrict__ C, int N, int K)
{
    extern __shared__ char smg[];
    g32_core(smg, A, W, C, N, K, blockIdx.y * 128, blockIdx.x * 128);
}

// ---------------------------------------------------------------------------
// RoPE + scale fold + round-to-TF32 in place on q, k, v.
// ---------------------------------------------------------------------------
__global__ __launch_bounds__(256) void rope_tf32(
    float* __restrict__ q, float* __restrict__ k, float* __restrict__ v,
    const float* __restrict__ cosb, const float* __restrict__ sinb,
    const float* __restrict__ temp)
{
    const int token = blockIdx.x;
    const int t = token & (T_ - 1);
    const float SC = 0.08838834764831845f * 1.4426950408889634f;
    for (int s = threadIdx.x; s < 1536; s += blockDim.x) {
        const int head = s >> 6;
        const int i = s & 63;
        float* base;
        float scale = 1.0f;
        bool dorope = true;
        if (head < 16) {
            base = q + ((size_t)token * H_ + head) * DH_;
            scale = temp[head] * SC;
        } else if (head < 20) {
            base = k + ((size_t)token * HKV_ + (head - 16)) * DH_;
        } else {
            base = v + ((size_t)token * HKV_ + (head - 20)) * DH_;
            dorope = false;
        }
        if (dorope && i < 32) {
            const float c  = cosb[t*32 + i];
            const float sn = sinb[t*32 + i];
            const float x1 = base[2*i];
            const float x2 = base[2*i + 1];
            base[2*i]     = tf32r((x1*c - x2*sn) * scale);
            base[2*i + 1] = tf32r((x1*sn + x2*c) * scale);
        } else {
            const int d = dorope ? 64 + (i - 32) * 2 : i * 2;
            base[d]     = tf32r(base[d] * scale);
            base[d + 1] = tf32r(base[d + 1] * scale);
        }
    }
}

// ---------------------------------------------------------------------------
// TF32 tensor-core causal GQA flash attention (proven round-8 kernel;
// epilogue writes tf32-rounded fp32 att).
// ---------------------------------------------------------------------------
#define KOFF0 0
#define KOFF1 8448
#define VOFF0 16896
#define VOFF1 25600
#define POFF  34304
#define ATTN_SMEM_B ((POFF + 8704) * 4)

__global__ __launch_bounds__(256, 1) void attn_tc(
    const float* __restrict__ Qg, const float* __restrict__ Kg,
    const float* __restrict__ Vg, float* __restrict__ att)
{
    extern __shared__ float sm[];
    const uint32_t sbase = (uint32_t)__cvta_generic_to_shared(sm);
    const int qt = 15 - blockIdx.x;
    const int h = blockIdx.y, b = blockIdx.z;
    const int kvh = h >> 2;
    const int tid = threadIdx.x;
    const int warp = tid >> 5, lane = tid & 31;
    const int g4 = lane >> 2, c4 = lane & 3;
    const int qrow0 = qt * 128 + warp * 16;
    const int nk = 2 * qt + 2;

    uint32_t qf[16][4];
    {
        const float* Q0 = Qg + ((size_t)(b*T_ + qrow0 + g4)*H_ + h)*DH_;
        const float* Q1 = Q0 + (size_t)8*H_*DH_;
#pragma unroll
        for (int kc = 0; kc < 16; kc++) {
            const int c0 = kc*8 + c4;
            qf[kc][0] = __float_as_uint(__ldg(Q0 + c0));
            qf[kc][1] = __float_as_uint(__ldg(Q1 + c0));
            qf[kc][2] = __float_as_uint(__ldg(Q0 + c0 + 4));
            qf[kc][3] = __float_as_uint(__ldg(Q1 + c0 + 4));
        }
    }

    float o[16][4];
#pragma unroll
    for (int dt = 0; dt < 16; dt++)
#pragma unroll
        for (int r = 0; r < 4; r++) o[dt][r] = 0.f;
    float m0 = -1e30f, m1 = -1e30f, l0 = 0.f, l1 = 0.f;

    float* Ps = sm + POFF + warp * 1088;

    {
        const size_t kvoff = ((size_t)(b*T_)*HKV_ + kvh)*DH_;
#pragma unroll
        for (int i = 0; i < 8; i++) {
            const int idx = tid + i*256, row = idx >> 5, cc = (idx & 31)*4;
            cp_async16(sbase + (uint32_t)(KOFF0 + row*132 + cc)*4,
                       Kg + kvoff + (size_t)row*NKV_ + cc);
        }
        cp_commit();
#pragma unroll
        for (int i = 0; i < 8; i++) {
            const int idx = tid + i*256, row = idx >> 5, cc = (idx & 31)*4;
            cp_async16(sbase + (uint32_t)(VOFF0 + row*136 + cc)*4,
                       Vg + kvoff + (size_t)row*NKV_ + cc);
        }
        cp_commit();
    }

    for (int kt = 0; kt < nk; kt++) {
        const int kc0 = kt * 64;
        const bool skip = (kc0 > qrow0 + 15);
        cp_wait<1>();
        __syncthreads();

        float sacc[8][4];
        if (!skip) {
#pragma unroll
            for (int nt = 0; nt < 8; nt++)
#pragma unroll
                for (int r = 0; r < 4; r++) sacc[nt][r] = 0.f;
            const float* Ksm = sm + ((kt & 1) ? KOFF1 : KOFF0);
#pragma unroll
            for (int kc = 0; kc < 16; kc++) {
                const int dk = kc*8 + c4;
#pragma unroll
                for (int nt = 0; nt < 8; nt++) {
                    const float* kp = Ksm + (nt*8 + g4)*132 + dk;
                    mma_tf32(sacc[nt], qf[kc],
                             __float_as_uint(kp[0]), __float_as_uint(kp[4]));
                }
            }
        }

        if (kt + 1 < nk) {
            const size_t kvoff = ((size_t)(b*T_ + kc0 + 64)*HKV_ + kvh)*DH_;
            const uint32_t kb = sbase + (uint32_t)(((kt+1)&1) ? KOFF1 : KOFF0)*4;
#pragma unroll
            for (int i = 0; i < 8; i++) {
                const int idx = tid + i*256, row = idx >> 5, cc = (idx & 31)*4;
                cp_async16(kb + (uint32_t)(row*132 + cc)*4,
                           Kg + kvoff + (size_t)row*NKV_ + cc);
            }
            cp_commit();
        }

        if (!skip) {
            if (kc0 + 63 > qrow0) {
#pragma unroll
                for (int nt = 0; nt < 8; nt++) {
                    const int cc = kc0 + nt*8 + 2*c4;
                    const int r0 = qrow0 + g4, r1 = r0 + 8;
                    if (cc     > r0) sacc[nt][0] = -1e30f;
                    if (cc + 1 > r0) sacc[nt][1] = -1e30f;
                    if (cc     > r1) sacc[nt][2] = -1e30f;
                    if (cc + 1 > r1) sacc[nt][3] = -1e30f;
                }
            }
            float rm0 = -1e30f, rm1 = -1e30f;
#pragma unroll
            for (int nt = 0; nt < 8; nt++) {
                rm0 = fmaxf(rm0, fmaxf(sacc[nt][0], sacc[nt][1]));
                rm1 = fmaxf(rm1, fmaxf(sacc[nt][2], sacc[nt][3]));
            }
#pragma unroll
            for (int off = 1; off <= 2; off <<= 1) {
                rm0 = fmaxf(rm0, __shfl_xor_sync(0xffffffffu, rm0, off));
                rm1 = fmaxf(rm1, __shfl_xor_sync(0xffffffffu, rm1, off));
            }
            const float mn0 = fmaxf(m0, rm0), mn1 = fmaxf(m1, rm1);
            const float a0 = fexp2(m0 - mn0), a1 = fexp2(m1 - mn1);
            m0 = mn0; m1 = mn1;
            float rs0 = 0.f, rs1 = 0.f;
#pragma unroll
            for (int nt = 0; nt < 8; nt++) {
                float p0 = fexp2(sacc[nt][0] - mn0);
                float p1 = fexp2(sacc[nt][1] - mn0);
                float p2 = fexp2(sacc[nt][2] - mn1);
                float p3 = fexp2(sacc[nt][3] - mn1);
                rs0 += p0 + p1; rs1 += p2 + p3;
                float* pr = Ps + g4*68 + nt*8 + 2*c4;
                *(float2*)pr = make_float2(__uint_as_float(f2tf32(p0)),
                                           __uint_as_float(f2tf32(p1)));
                *(float2*)(pr + 8*68) = make_float2(__uint_as_float(f2tf32(p2)),
                                                    __uint_as_float(f2tf32(p3)));
            }
#pragma unroll
            for (int off = 1; off <= 2; off <<= 1) {
                rs0 += __shfl_xor_sync(0xffffffffu, rs0, off);
                rs1 += __shfl_xor_sync(0xffffffffu, rs1, off);
            }
            l0 = l0 * a0 + rs0;
            l1 = l1 * a1 + rs1;
#pragma unroll
            for (int dt = 0; dt < 16; dt++) {
                o[dt][0] *= a0; o[dt][1] *= a0;
                o[dt][2] *= a1; o[dt][3] *= a1;
            }
        }

        if (kt + 1 < nk) cp_wait<1>(); else cp_wait<0>();
        __syncthreads();

        if (!skip) {
            const float* Vsm = sm + ((kt & 1) ? VOFF1 : VOFF0);
#pragma unroll
            for (int kc = 0; kc < 8; kc++) {
                uint32_t af[4];
                const float* pr = Ps + g4*68 + kc*8 + c4;
                af[0] = __float_as_uint(pr[0]);
                af[1] = __float_as_uint(pr[8*68]);
                af[2] = __float_as_uint(pr[4]);
                af[3] = __float_as_uint(pr[8*68 + 4]);
#pragma unroll
                for (int dt = 0; dt < 16; dt++) {
                    const float* vp = Vsm + (kc*8 + c4)*136 + dt*8 + g4;
                    mma_tf32(o[dt], af,
                             __float_as_uint(vp[0]), __float_as_uint(vp[4*136]));
                }
            }
        }

        if (kt + 1 < nk) {
            const size_t kvoff = ((size_t)(b*T_ + kc0 + 64)*HKV_ + kvh)*DH_;
            const uint32_t vb = sbase + (uint32_t)(((kt+1)&1) ? VOFF1 : VOFF0)*4;
#pragma unroll
            for (int i = 0; i < 8; i++) {
                const int idx = tid + i*256, row = idx >> 5, cc = (idx & 31)*4;
                cp_async16(vb + (uint32_t)(row*136 + cc)*4,
                           Vg + kvoff + (size_t)row*NKV_ + cc);
            }
            cp_commit();
        }
    }

    // epilogue: /l, tf32-round, write fp32 att for the Wo tf32 GEMM
    const float inv0 = 1.f / l0, inv1 = 1.f / l1;
    float* r0 = att + ((size_t)(b*T_ + qrow0 + g4))*NQ_ + h*DH_ + 2*c4;
    float* r1 = r0 + (size_t)8*NQ_;
#pragma unroll
    for (int dt = 0; dt < 16; dt++) {
        *(float2*)(r0 + dt*8) = make_float2(tf32r(o[dt][0]*inv0), tf32r(o[dt][1]*inv0));
        *(float2*)(r1 + dt*8) = make_float2(tf32r(o[dt][2]*inv1), tf32r(o[dt][3]*inv1));
    }
}

// ---------------------------------------------------------------------------
extern "C" void kernel_launch(void* const* d_in, const int* in_sizes, int n_in,
                              void* d_out, int out_size)
{
    const float* x    = (const float*)d_in[0];
    const float* cosb = (const float*)d_in[1];
    const float* sinb = (const float*)d_in[2];
    const float* Wq   = (const float*)d_in[3];
    const float* Wk   = (const float*)d_in[4];
    const float* Wv   = (const float*)d_in[5];
    const float* Wo   = (const float*)d_in[6];
    const float* temp = (const float*)d_in[7];
    float* out = (float*)d_out;

    float *q, *k, *v, *att, *x32, *wq32, *wk32, *wv32, *wo32;
    cudaGetSymbolAddress((void**)&q,   g_q);
    cudaGetSymbolAddress((void**)&k,   g_k);
    cudaGetSymbolAddress((void**)&v,   g_v);
    cudaGetSymbolAddress((void**)&att, g_att);
    cudaGetSymbolAddress((void**)&x32, g_x32);
    cudaGetSymbolAddress((void**)&wq32, g_wq32);
    cudaGetSymbolAddress((void**)&wk32, g_wk32);
    cudaGetSymbolAddress((void**)&wv32, g_wv32);
    cudaGetSymbolAddress((void**)&wo32, g_wo32);

    cudaFuncSetAttribute(gemm_qkv32,
                         cudaFuncAttributeMaxDynamicSharedMemorySize, GEMM32_SMEM);
    cudaFuncSetAttribute(gemm32_nt,
                         cudaFuncAttributeMaxDynamicSharedMemorySize, GEMM32_SMEM);
    cudaFuncSetAttribute(attn_tc,
                         cudaFuncAttributeMaxDynamicSharedMemorySize, ATTN_SMEM_B);

    // Round operands to tf32
    t32_kernel<<<(M_*D_ + 255)/256,   256>>>(x,  x32,  M_*D_);
    t32_kernel<<<(NQ_*D_ + 255)/256,  256>>>(Wq, wq32, NQ_*D_);
    t32_kernel<<<(NKV_*D_ + 255)/256, 256>>>(Wk, wk32, NKV_*D_);
    t32_kernel<<<(NKV_*D_ + 255)/256, 256>>>(Wv, wv32, NKV_*D_);
    t32_kernel<<<(D_*D_ + 255)/256,   256>>>(Wo, wo32, D_*D_);

    // QKV projections (single-pass TF32 tensor cores, fused)
    gemm_qkv32<<<dim3(24, M_/128), 256, GEMM32_SMEM>>>(
        x32, wq32, wk32, wv32, q, k, v);

    // RoPE + temp + tf32 round
    rope_tf32<<<M_, 256>>>(q, k, v, cosb, sinb, temp);

    // Flash attention (TF32 tensor cores)
    attn_tc<<<dim3(16, H_, B_), 256, ATTN_SMEM_B>>>(q, k, v, att);

    // Output projection (single-pass TF32)
    gemm32_nt<<<dim3(D_/128, M_/128), 256, GEMM32_SMEM>>>(att, wo32, out, D_, D_);
}

// round 14
// speedup vs baseline: 1.9537x; 1.0748x over previous
#include <cuda_runtime.h>
#include <cuda_bf16.h>
#include <cstdint>

// Problem constants
#define B_  2
#define T_  2048
#define D_  2048
#define H_  16
#define HKV_ 4
#define DH_ 128
#define M_  (B_*T_)
#define NQ_ (H_*DH_)
#define NKV_ (HKV_*DH_)

// fp32 scratch
__device__ float g_q[(size_t)M_ * NQ_];
__device__ float g_k[(size_t)M_ * NKV_];
__device__ float g_v[(size_t)M_ * NKV_];
__device__ float g_att[(size_t)M_ * NQ_];
// tf32-rounded fp32 operands
__device__ float g_x32[(size_t)M_ * D_];
__device__ float g_wq32[(size_t)NQ_ * D_];
__device__ float g_wk32[(size_t)NKV_ * D_];
__device__ float g_wv32[(size_t)NKV_ * D_];
__device__ float g_wo32[(size_t)D_ * D_];

// ---------------------------------------------------------------------------
// PTX helpers (compute_103-safe)
// ---------------------------------------------------------------------------
__device__ __forceinline__ void cp_async16(uint32_t s, const void* g) {
    asm volatile("cp.async.cg.shared.global [%0], [%1], 16;\n" :: "r"(s), "l"(g));
}
__device__ __forceinline__ void cp_commit() {
    asm volatile("cp.async.commit_group;\n");
}
template<int N> __device__ __forceinline__ void cp_wait() {
    asm volatile("cp.async.wait_group %0;\n" :: "n"(N));
}
__device__ __forceinline__ void ldsm_x4(uint32_t& r0, uint32_t& r1,
                                        uint32_t& r2, uint32_t& r3, uint32_t a) {
    asm volatile("ldmatrix.sync.aligned.m8n8.x4.shared.b16 {%0,%1,%2,%3}, [%4];\n"
                 : "=r"(r0), "=r"(r1), "=r"(r2), "=r"(r3) : "r"(a));
}
__device__ __forceinline__ void mma_tf32(float* d, const uint32_t* a,
                                         uint32_t b0, uint32_t b1) {
    asm volatile(
        "mma.sync.aligned.m16n8k8.row.col.f32.tf32.tf32.f32 "
        "{%0,%1,%2,%3},{%4,%5,%6,%7},{%8,%9},{%0,%1,%2,%3};\n"
        : "+f"(d[0]), "+f"(d[1]), "+f"(d[2]), "+f"(d[3])
        : "r"(a[0]), "r"(a[1]), "r"(a[2]), "r"(a[3]), "r"(b0), "r"(b1));
}
__device__ __forceinline__ uint32_t f2tf32(float x) {
    uint32_t r;
    asm("cvt.rna.tf32.f32 %0, %1;" : "=r"(r) : "f"(x));
    return r;
}
__device__ __forceinline__ float tf32r(float x) { return __uint_as_float(f2tf32(x)); }
__device__ __forceinline__ float fexp2(float x) {
    float y;
    asm("ex2.approx.ftz.f32 %0, %1;" : "=f"(y) : "f"(x));
    return y;
}

// ---------------------------------------------------------------------------
// Round fp32 -> tf32-in-fp32
// ---------------------------------------------------------------------------
__global__ __launch_bounds__(256) void t32_kernel(
    const float* __restrict__ in, float* __restrict__ out, int n)
{
    int i = blockIdx.x * blockDim.x + threadIdx.x;
    if (i < n) out[i] = tf32r(in[i]);
}

// ---------------------------------------------------------------------------
// TF32 NT GEMM core: C[m,n] = sum_k A[m,k]*W[n,k]  (fp32 out, single pass)
// 256x128 tile, BK=64, 256 threads (8 warps, 4x2), warp tile 64x64,
// mma.m16n8k8.tf32, 2-stage cp.async, 272B smem row stride.
// ---------------------------------------------------------------------------
#define BK32     64
#define ROWB     272                   // 64 f32 + 16B pad
#define TILE_A32 (256*ROWB)            // 69632 B
#define TILE_W32 (128*ROWB)            // 34816 B
#define STAGE32  (TILE_A32 + TILE_W32) // 104448 B
#define GEMM32_SMEM (2*STAGE32)        // 208896 B

__device__ __forceinline__ void g32_load_stage(
    uint32_t sa, const float* __restrict__ A, const float* __restrict__ W,
    int bm, int bn, int K, int k0, int tid)
{
#pragma unroll
    for (int t = 0; t < 16; t++) {          // A: 256 rows x 64 f32
        const int idx = tid + t * 256;      // 0..4095
        const int row = idx >> 4;           // 0..255
        const int c4  = (idx & 15) * 4;
        cp_async16(sa + (uint32_t)(row * ROWB + c4 * 4),
                   A + (size_t)(bm + row) * K + k0 + c4);
    }
#pragma unroll
    for (int t = 0; t < 8; t++) {           // W: 128 rows x 64 f32
        const int idx = tid + t * 256;      // 0..2047
        const int row = idx >> 4;           // 0..127
        const int c4  = (idx & 15) * 4;
        cp_async16(sa + (uint32_t)TILE_A32 + (uint32_t)(row * ROWB + c4 * 4),
                   W + (size_t)(bn + row) * K + k0 + c4);
    }
}

__device__ __forceinline__ void g32_core(
    char* smg, const float* __restrict__ A, const float* __restrict__ W,
    float* __restrict__ C, int N, int K, int bm, int bn)
{
    const int tid  = threadIdx.x;
    const int warp = tid >> 5, lane = tid & 31;
    const int wm = (warp >> 1) * 64;        // 4 m-warps
    const int wn = (warp & 1) * 64;         // 2 n-warps
    const uint32_t sbase = (uint32_t)__cvta_generic_to_shared(smg);

    float acc[4][8][4];
#pragma unroll
    for (int i = 0; i < 4; i++)
#pragma unroll
        for (int j = 0; j < 8; j++)
#pragma unroll
            for (int r = 0; r < 4; r++) acc[i][j][r] = 0.f;

    const int arow = (lane & 7) + ((lane >> 3) & 1) * 8;   // A m-row within 16
    const int acb  = ((lane >> 4) & 1) * 16;               // A k byte offset
    const int brow = (lane & 7) + ((lane >> 4) & 1) * 8;   // B n-row within 16
    const int bcb  = ((lane >> 3) & 1) * 16;               // B k byte offset

    g32_load_stage(sbase, A, W, bm, bn, K, 0, tid);
    cp_commit();

    const int NC = K / BK32;
    for (int c = 0; c < NC; c++) {
        if (c + 1 < NC) {
            g32_load_stage(sbase + ((c + 1) & 1) * STAGE32,
                           A, W, bm, bn, K, (c + 1) * BK32, tid);
            cp_commit();
            cp_wait<1>();
        } else {
            cp_wait<0>();
        }
        __syncthreads();

        const uint32_t aA = sbase + (c & 1) * STAGE32;
        const uint32_t aW = aA + TILE_A32;

#pragma unroll
        for (int ks = 0; ks < 8; ks++) {
            const int kb = ks * 32;        // 8 f32 per k-step
            uint32_t b[8][2];
#pragma unroll
            for (int jj = 0; jj < 4; jj++) {
                const uint32_t ad = aW + (uint32_t)((wn + jj*16 + brow) * ROWB) + bcb + kb;
                ldsm_x4(b[2*jj][0], b[2*jj][1], b[2*jj+1][0], b[2*jj+1][1], ad);
            }
            uint32_t a[4][4];
#pragma unroll
            for (int i = 0; i < 4; i++) {
                const uint32_t ad = aA + (uint32_t)((wm + i*16 + arow) * ROWB) + acb + kb;
                ldsm_x4(a[i][0], a[i][1], a[i][2], a[i][3], ad);
            }
#pragma unroll
            for (int i = 0; i < 4; i++)
#pragma unroll
                for (int j = 0; j < 8; j++)
                    mma_tf32(acc[i][j], a[i], b[j][0], b[j][1]);
        }
        __syncthreads();
    }

    const int er = lane >> 2, ec = (lane & 3) * 2;
#pragma unroll
    for (int i = 0; i < 4; i++)
#pragma unroll
        for (int j = 0; j < 8; j++) {
            float* p0 = C + (size_t)(bm + wm + 16*i + er) * N + bn + wn + 8*j + ec;
            float* p1 = p0 + (size_t)8 * N;
            *(float2*)p0 = make_float2(acc[i][j][0], acc[i][j][1]);
            *(float2*)p1 = make_float2(acc[i][j][2], acc[i][j][3]);
        }
}

// Fused QKV projection: grid (24, 16). bx<16 -> Q, 16..19 -> K, 20..23 -> V.
__global__ __launch_bounds__(256) void gemm_qkv32(
    const float* __restrict__ x32,
    const float* __restrict__ wq32, const float* __restrict__ wk32,
    const float* __restrict__ wv32,
    float* __restrict__ q, float* __restrict__ k, float* __restrict__ v)
{
    extern __shared__ char smg[];
    const int bx = blockIdx.x;
    const float* W;
    float* C;
    int N, bn;
    if (bx < 16)      { W = wq32; C = q; N = NQ_;  bn = bx * 128; }
    else if (bx < 20) { W = wk32; C = k; N = NKV_; bn = (bx - 16) * 128; }
    else              { W = wv32; C = v; N = NKV_; bn = (bx - 20) * 128; }
    g32_core(smg, x32, W, C, N, D_, blockIdx.y * 256, bn);
}

// Generic tf32 GEMM (used for Wo)
__global__ __launch_bounds__(256) void gemm32_nt(
    const float* __restrict__ A, const float* __restrict__ W,
    float* __restrict__ C, int N, int K)
{
    extern __shared__ char smg[];
    g32_core(smg, A, W, C, N, K, blockIdx.y * 256, blockIdx.x * 128);
}

// ---------------------------------------------------------------------------
// RoPE + scale fold + round-to-TF32 in place on q, k, v.
// ---------------------------------------------------------------------------
__global__ __launch_bounds__(256) void rope_tf32(
    float* __restrict__ q, float* __restrict__ k, float* __restrict__ v,
    const float* __restrict__ cosb, const float* __restrict__ sinb,
    const float* __restrict__ temp)
{
    const int token = blockIdx.x;
    const int t = token & (T_ - 1);
    const float SC = 0.08838834764831845f * 1.4426950408889634f;
    for (int s = threadIdx.x; s < 1536; s += blockDim.x) {
        const int head = s >> 6;
        const int i = s & 63;
        float* base;
        float scale = 1.0f;
        bool dorope = true;
        if (head < 16) {
            base = q + ((size_t)token * H_ + head) * DH_;
            scale = temp[head] * SC;
        } else if (head < 20) {
            base = k + ((size_t)token * HKV_ + (head - 16)) * DH_;
        } else {
            base = v + ((size_t)token * HKV_ + (head - 20)) * DH_;
            dorope = false;
        }
        if (dorope && i < 32) {
            const float c  = cosb[t*32 + i];
            const float sn = sinb[t*32 + i];
            const float x1 = base[2*i];
            const float x2 = base[2*i + 1];
            base[2*i]     = tf32r((x1*c - x2*sn) * scale);
            base[2*i + 1] = tf32r((x1*sn + x2*c) * scale);
        } else {
            const int d = dorope ? 64 + (i - 32) * 2 : i * 2;
            base[d]     = tf32r(base[d] * scale);
            base[d + 1] = tf32r(base[d + 1] * scale);
        }
    }
}

// ---------------------------------------------------------------------------
// TF32 tensor-core causal GQA flash attention (proven round-8 kernel;
// epilogue writes tf32-rounded fp32 att).
// ---------------------------------------------------------------------------
#define KOFF0 0
#define KOFF1 8448
#define VOFF0 16896
#define VOFF1 25600
#define POFF  34304
#define ATTN_SMEM_B ((POFF + 8704) * 4)

__global__ __launch_bounds__(256, 1) void attn_tc(
    const float* __restrict__ Qg, const float* __restrict__ Kg,
    const float* __restrict__ Vg, float* __restrict__ att)
{
    extern __shared__ float sm[];
    const uint32_t sbase = (uint32_t)__cvta_generic_to_shared(sm);
    const int qt = 15 - blockIdx.x;
    const int h = blockIdx.y, b = blockIdx.z;
    const int kvh = h >> 2;
    const int tid = threadIdx.x;
    const int warp = tid >> 5, lane = tid & 31;
    const int g4 = lane >> 2, c4 = lane & 3;
    const int qrow0 = qt * 128 + warp * 16;
    const int nk = 2 * qt + 2;

    uint32_t qf[16][4];
    {
        const float* Q0 = Qg + ((size_t)(b*T_ + qrow0 + g4)*H_ + h)*DH_;
        const float* Q1 = Q0 + (size_t)8*H_*DH_;
#pragma unroll
        for (int kc = 0; kc < 16; kc++) {
            const int c0 = kc*8 + c4;
            qf[kc][0] = __float_as_uint(__ldg(Q0 + c0));
            qf[kc][1] = __float_as_uint(__ldg(Q1 + c0));
            qf[kc][2] = __float_as_uint(__ldg(Q0 + c0 + 4));
            qf[kc][3] = __float_as_uint(__ldg(Q1 + c0 + 4));
        }
    }

    float o[16][4];
#pragma unroll
    for (int dt = 0; dt < 16; dt++)
#pragma unroll
        for (int r = 0; r < 4; r++) o[dt][r] = 0.f;
    float m0 = -1e30f, m1 = -1e30f, l0 = 0.f, l1 = 0.f;

    float* Ps = sm + POFF + warp * 1088;

    {
        const size_t kvoff = ((size_t)(b*T_)*HKV_ + kvh)*DH_;
#pragma unroll
        for (int i = 0; i < 8; i++) {
            const int idx = tid + i*256, row = idx >> 5, cc = (idx & 31)*4;
            cp_async16(sbase + (uint32_t)(KOFF0 + row*132 + cc)*4,
                       Kg + kvoff + (size_t)row*NKV_ + cc);
        }
        cp_commit();
#pragma unroll
        for (int i = 0; i < 8; i++) {
            const int idx = tid + i*256, row = idx >> 5, cc = (idx & 31)*4;
            cp_async16(sbase + (uint32_t)(VOFF0 + row*136 + cc)*4,
                       Vg + kvoff + (size_t)row*NKV_ + cc);
        }
        cp_commit();
    }

    for (int kt = 0; kt < nk; kt++) {
        const int kc0 = kt * 64;
        const bool skip = (kc0 > qrow0 + 15);
        cp_wait<1>();
        __syncthreads();

        float sacc[8][4];
        if (!skip) {
#pragma unroll
            for (int nt = 0; nt < 8; nt++)
#pragma unroll
                for (int r = 0; r < 4; r++) sacc[nt][r] = 0.f;
            const float* Ksm = sm + ((kt & 1) ? KOFF1 : KOFF0);
#pragma unroll
            for (int kc = 0; kc < 16; kc++) {
                const int dk = kc*8 + c4;
#pragma unroll
                for (int nt = 0; nt < 8; nt++) {
                    const float* kp = Ksm + (nt*8 + g4)*132 + dk;
                    mma_tf32(sacc[nt], qf[kc],
                             __float_as_uint(kp[0]), __float_as_uint(kp[4]));
                }
            }
        }

        if (kt + 1 < nk) {
            const size_t kvoff = ((size_t)(b*T_ + kc0 + 64)*HKV_ + kvh)*DH_;
            const uint32_t kb = sbase + (uint32_t)(((kt+1)&1) ? KOFF1 : KOFF0)*4;
#pragma unroll
            for (int i = 0; i < 8; i++) {
                const int idx = tid + i*256, row = idx >> 5, cc = (idx & 31)*4;
                cp_async16(kb + (uint32_t)(row*132 + cc)*4,
                           Kg + kvoff + (size_t)row*NKV_ + cc);
            }
            cp_commit();
        }

        if (!skip) {
            if (kc0 + 63 > qrow0) {
#pragma unroll
                for (int nt = 0; nt < 8; nt++) {
                    const int cc = kc0 + nt*8 + 2*c4;
                    const int r0 = qrow0 + g4, r1 = r0 + 8;
                    if (cc     > r0) sacc[nt][0] = -1e30f;
                    if (cc + 1 > r0) sacc[nt][1] = -1e30f;
                    if (cc     > r1) sacc[nt][2] = -1e30f;
                    if (cc + 1 > r1) sacc[nt][3] = -1e30f;
                }
            }
            float rm0 = -1e30f, rm1 = -1e30f;
#pragma unroll
            for (int nt = 0; nt < 8; nt++) {
                rm0 = fmaxf(rm0, fmaxf(sacc[nt][0], sacc[nt][1]));
                rm1 = fmaxf(rm1, fmaxf(sacc[nt][2], sacc[nt][3]));
            }
#pragma unroll
            for (int off = 1; off <= 2; off <<= 1) {
                rm0 = fmaxf(rm0, __shfl_xor_sync(0xffffffffu, rm0, off));
                rm1 = fmaxf(rm1, __shfl_xor_sync(0xffffffffu, rm1, off));
            }
            const float mn0 = fmaxf(m0, rm0), mn1 = fmaxf(m1, rm1);
            const float a0 = fexp2(m0 - mn0), a1 = fexp2(m1 - mn1);
            m0 = mn0; m1 = mn1;
            float rs0 = 0.f, rs1 = 0.f;
#pragma unroll
            for (int nt = 0; nt < 8; nt++) {
                float p0 = fexp2(sacc[nt][0] - mn0);
                float p1 = fexp2(sacc[nt][1] - mn0);
                float p2 = fexp2(sacc[nt][2] - mn1);
                float p3 = fexp2(sacc[nt][3] - mn1);
                rs0 += p0 + p1; rs1 += p2 + p3;
                float* pr = Ps + g4*68 + nt*8 + 2*c4;
                *(float2*)pr = make_float2(__uint_as_float(f2tf32(p0)),
                                           __uint_as_float(f2tf32(p1)));
                *(float2*)(pr + 8*68) = make_float2(__uint_as_float(f2tf32(p2)),
                                                    __uint_as_float(f2tf32(p3)));
            }
#pragma unroll
            for (int off = 1; off <= 2; off <<= 1) {
                rs0 += __shfl_xor_sync(0xffffffffu, rs0, off);
                rs1 += __shfl_xor_sync(0xffffffffu, rs1, off);
            }
            l0 = l0 * a0 + rs0;
            l1 = l1 * a1 + rs1;
#pragma unroll
            for (int dt = 0; dt < 16; dt++) {
                o[dt][0] *= a0; o[dt][1] *= a0;
                o[dt][2] *= a1; o[dt][3] *= a1;
            }
        }

        if (kt + 1 < nk) cp_wait<1>(); else cp_wait<0>();
        __syncthreads();

        if (!skip) {
            const float* Vsm = sm + ((kt & 1) ? VOFF1 : VOFF0);
#pragma unroll
            for (int kc = 0; kc < 8; kc++) {
                uint32_t af[4];
                const float* pr = Ps + g4*68 + kc*8 + c4;
                af[0] = __float_as_uint(pr[0]);
                af[1] = __float_as_uint(pr[8*68]);
                af[2] = __float_as_uint(pr[4]);
                af[3] = __float_as_uint(pr[8*68 + 4]);
#pragma unroll
                for (int dt = 0; dt < 16; dt++) {
                    const float* vp = Vsm + (kc*8 + c4)*136 + dt*8 + g4;
                    mma_tf32(o[dt], af,
                             __float_as_uint(vp[0]), __float_as_uint(vp[4*136]));
                }
            }
        }

        if (kt + 1 < nk) {
            const size_t kvoff = ((size_t)(b*T_ + kc0 + 64)*HKV_ + kvh)*DH_;
            const uint32_t vb = sbase + (uint32_t)(((kt+1)&1) ? VOFF1 : VOFF0)*4;
#pragma unroll
            for (int i = 0; i < 8; i++) {
                const int idx = tid + i*256, row = idx >> 5, cc = (idx & 31)*4;
                cp_async16(vb + (uint32_t)(row*136 + cc)*4,
                           Vg + kvoff + (size_t)row*NKV_ + cc);
            }
            cp_commit();
        }
    }

    // epilogue: /l, tf32-round, write fp32 att for the Wo tf32 GEMM
    const float inv0 = 1.f / l0, inv1 = 1.f / l1;
    float* r0 = att + ((size_t)(b*T_ + qrow0 + g4))*NQ_ + h*DH_ + 2*c4;
    float* r1 = r0 + (size_t)8*NQ_;
#pragma unroll
    for (int dt = 0; dt < 16; dt++) {
        *(float2*)(r0 + dt*8) = make_float2(tf32r(o[dt][0]*inv0), tf32r(o[dt][1]*inv0));
        *(float2*)(r1 + dt*8) = make_float2(tf32r(o[dt][2]*inv1), tf32r(o[dt][3]*inv1));
    }
}

// ---------------------------------------------------------------------------
extern "C" void kernel_launch(void* const* d_in, const int* in_sizes, int n_in,
                              void* d_out, int out_size)
{
    const float* x    = (const float*)d_in[0];
    const float* cosb = (const float*)d_in[1];
    const float* sinb = (const float*)d_in[2];
    const float* Wq   = (const float*)d_in[3];
    const float* Wk   = (const float*)d_in[4];
    const float* Wv   = (const float*)d_in[5];
    const float* Wo   = (const float*)d_in[6];
    const float* temp = (const float*)d_in[7];
    float* out = (float*)d_out;

    float *q, *k, *v, *att, *x32, *wq32, *wk32, *wv32, *wo32;
    cudaGetSymbolAddress((void**)&q,   g_q);
    cudaGetSymbolAddress((void**)&k,   g_k);
    cudaGetSymbolAddress((void**)&v,   g_v);
    cudaGetSymbolAddress((void**)&att, g_att);
    cudaGetSymbolAddress((void**)&x32, g_x32);
    cudaGetSymbolAddress((void**)&wq32, g_wq32);
    cudaGetSymbolAddress((void**)&wk32, g_wk32);
    cudaGetSymbolAddress((void**)&wv32, g_wv32);
    cudaGetSymbolAddress((void**)&wo32, g_wo32);

    cudaFuncSetAttribute(gemm_qkv32,
                         cudaFuncAttributeMaxDynamicSharedMemorySize, GEMM32_SMEM);
    cudaFuncSetAttribute(gemm32_nt,
                         cudaFuncAttributeMaxDynamicSharedMemorySize, GEMM32_SMEM);
    cudaFuncSetAttribute(attn_tc,
                         cudaFuncAttributeMaxDynamicSharedMemorySize, ATTN_SMEM_B);

    // Round operands to tf32
    t32_kernel<<<(M_*D_ + 255)/256,   256>>>(x,  x32,  M_*D_);
    t32_kernel<<<(NQ_*D_ + 255)/256,  256>>>(Wq, wq32, NQ_*D_);
    t32_kernel<<<(NKV_*D_ + 255)/256, 256>>>(Wk, wk32, NKV_*D_);
    t32_kernel<<<(NKV_*D_ + 255)/256, 256>>>(Wv, wv32, NKV_*D_);
    t32_kernel<<<(D_*D_ + 255)/256,   256>>>(Wo, wo32, D_*D_);

    // QKV projections (single-pass TF32 tensor cores, fused, 256x128 tiles)
    gemm_qkv32<<<dim3(24, M_/256), 256, GEMM32_SMEM>>>(
        x32, wq32, wk32, wv32, q, k, v);

    // RoPE + temp + tf32 round
    rope_tf32<<<M_, 256>>>(q, k, v, cosb, sinb, temp);

    // Flash attention (TF32 tensor cores)
    attn_tc<<<dim3(16, H_, B_), 256, ATTN_SMEM_B>>>(q, k, v, att);

    // Output projection (single-pass TF32, 256x128 tiles)
    gemm32_nt<<<dim3(D_/128, M_/256), 256, GEMM32_SMEM>>>(att, wo32, out, D_, D_);
}

// round 15
// speedup vs baseline: 2.7860x; 1.4260x over previous
#include <cuda_runtime.h>
#include <cuda_fp16.h>
#include <cstdint>

// Problem constants
#define B_  2
#define T_  2048
#define D_  2048
#define H_  16
#define HKV_ 4
#define DH_ 128
#define M_  (B_*T_)
#define NQ_ (H_*DH_)
#define NKV_ (HKV_*DH_)

// fp32 scratch
__device__ float g_q[(size_t)M_ * NQ_];
__device__ float g_k[(size_t)M_ * NKV_];
__device__ float g_v[(size_t)M_ * NKV_];
// fp16 operands
__device__ __half g_xh[(size_t)M_ * D_];
__device__ __half g_wqh[(size_t)NQ_ * D_];
__device__ __half g_wkh[(size_t)NKV_ * D_];
__device__ __half g_wvh[(size_t)NKV_ * D_];
__device__ __half g_woh[(size_t)D_ * D_];
__device__ __half g_atth[(size_t)M_ * NQ_];

// ---------------------------------------------------------------------------
// PTX helpers (compute_103-safe)
// ---------------------------------------------------------------------------
__device__ __forceinline__ void cp_async16(uint32_t s, const void* g) {
    asm volatile("cp.async.cg.shared.global [%0], [%1], 16;\n" :: "r"(s), "l"(g));
}
__device__ __forceinline__ void cp_commit() {
    asm volatile("cp.async.commit_group;\n");
}
template<int N> __device__ __forceinline__ void cp_wait() {
    asm volatile("cp.async.wait_group %0;\n" :: "n"(N));
}
__device__ __forceinline__ void ldsm_x4(uint32_t& r0, uint32_t& r1,
                                        uint32_t& r2, uint32_t& r3, uint32_t a) {
    asm volatile("ldmatrix.sync.aligned.m8n8.x4.shared.b16 {%0,%1,%2,%3}, [%4];\n"
                 : "=r"(r0), "=r"(r1), "=r"(r2), "=r"(r3) : "r"(a));
}
__device__ __forceinline__ void mma_fp16(float* d, const uint32_t* a,
                                         uint32_t b0, uint32_t b1) {
    asm volatile(
        "mma.sync.aligned.m16n8k16.row.col.f32.f16.f16.f32 "
        "{%0,%1,%2,%3},{%4,%5,%6,%7},{%8,%9},{%0,%1,%2,%3};\n"
        : "+f"(d[0]), "+f"(d[1]), "+f"(d[2]), "+f"(d[3])
        : "r"(a[0]), "r"(a[1]), "r"(a[2]), "r"(a[3]), "r"(b0), "r"(b1));
}
__device__ __forceinline__ void mma_tf32(float* d, const uint32_t* a,
                                         uint32_t b0, uint32_t b1) {
    asm volatile(
        "mma.sync.aligned.m16n8k8.row.col.f32.tf32.tf32.f32 "
        "{%0,%1,%2,%3},{%4,%5,%6,%7},{%8,%9},{%0,%1,%2,%3};\n"
        : "+f"(d[0]), "+f"(d[1]), "+f"(d[2]), "+f"(d[3])
        : "r"(a[0]), "r"(a[1]), "r"(a[2]), "r"(a[3]), "r"(b0), "r"(b1));
}
__device__ __forceinline__ uint32_t f2tf32(float x) {
    uint32_t r;
    asm("cvt.rna.tf32.f32 %0, %1;" : "=r"(r) : "f"(x));
    return r;
}
__device__ __forceinline__ float tf32r(float x) { return __uint_as_float(f2tf32(x)); }
__device__ __forceinline__ float fexp2(float x) {
    float y;
    asm("ex2.approx.ftz.f32 %0, %1;" : "=f"(y) : "f"(x));
    return y;
}

// ---------------------------------------------------------------------------
// Convert fp32 -> fp16 (rn)
// ---------------------------------------------------------------------------
__global__ __launch_bounds__(256) void h16_kernel(
    const float* __restrict__ in, __half* __restrict__ out, int n)
{
    int i = blockIdx.x * blockDim.x + threadIdx.x;
    if (i < n) out[i] = __float2half_rn(in[i]);
}

// ---------------------------------------------------------------------------
// fp16 NT GEMM core: C[m,n] = sum_k A[m,k]*W[n,k]  (fp32 accumulate/out)
// 256x128 tile, BK=64, 256 threads (8 warps, 4x2), warp tile 64x64,
// mma.m16n8k16.f16, 2-stage cp.async, 144B smem row stride (proven layout).
// ---------------------------------------------------------------------------
#define BK_H     64
#define LDSRH    72                     // fp16 elems per smem row (144 B)
#define TILE_AH  (256*LDSRH*2)          // 36864 B
#define TILE_WH  (128*LDSRH*2)          // 18432 B
#define STAGE_H  (TILE_AH + TILE_WH)    // 55296 B
#define GEMMH_SMEM (2*STAGE_H)          // 110592 B

__device__ __forceinline__ void gh_load_stage(
    uint32_t sa, const __half* __restrict__ A, const __half* __restrict__ W,
    int bm, int bn, int K, int k0, int tid)
{
#pragma unroll
    for (int t = 0; t < 8; t++) {           // A: 256 rows x 64 fp16
        const int idx = tid + t * 256;      // 0..2047
        const int row = idx >> 3;           // 0..255
        const int c8  = (idx & 7) * 8;      // fp16 col, 16B chunks
        cp_async16(sa + (uint32_t)(row * LDSRH + c8) * 2,
                   A + (size_t)(bm + row) * K + k0 + c8);
    }
#pragma unroll
    for (int t = 0; t < 4; t++) {           // W: 128 rows x 64 fp16
        const int idx = tid + t * 256;      // 0..1023
        const int row = idx >> 3;           // 0..127
        const int c8  = (idx & 7) * 8;
        cp_async16(sa + (uint32_t)TILE_AH + (uint32_t)(row * LDSRH + c8) * 2,
                   W + (size_t)(bn + row) * K + k0 + c8);
    }
}

__device__ __forceinline__ void gh_core(
    char* smg, const __half* __restrict__ A, const __half* __restrict__ W,
    float* __restrict__ C, int N, int K, int bm, int bn)
{
    const int tid  = threadIdx.x;
    const int warp = tid >> 5, lane = tid & 31;
    const int wm = (warp >> 1) * 64;        // 4 m-warps
    const int wn = (warp & 1) * 64;         // 2 n-warps
    const uint32_t sbase = (uint32_t)__cvta_generic_to_shared(smg);

    float acc[4][8][4];
#pragma unroll
    for (int i = 0; i < 4; i++)
#pragma unroll
        for (int j = 0; j < 8; j++)
#pragma unroll
            for (int r = 0; r < 4; r++) acc[i][j][r] = 0.f;

    const int arow = (lane & 7) + ((lane >> 3) & 1) * 8;   // A m-row within 16
    const int acb  = ((lane >> 4) & 1) * 16;               // A k byte offset
    const int brow = (lane & 7) + ((lane >> 4) & 1) * 8;   // B n-row within 16
    const int bcb  = ((lane >> 3) & 1) * 16;               // B k byte offset

    gh_load_stage(sbase, A, W, bm, bn, K, 0, tid);
    cp_commit();

    const int NC = K / BK_H;
    for (int c = 0; c < NC; c++) {
        if (c + 1 < NC) {
            gh_load_stage(sbase + ((c + 1) & 1) * STAGE_H,
                          A, W, bm, bn, K, (c + 1) * BK_H, tid);
            cp_commit();
            cp_wait<1>();
        } else {
            cp_wait<0>();
        }
        __syncthreads();

        const uint32_t aA = sbase + (c & 1) * STAGE_H;
        const uint32_t aW = aA + TILE_AH;

#pragma unroll
        for (int ks = 0; ks < 4; ks++) {
            const int kb = ks * 32;        // 16 fp16 per k-step
            uint32_t b[8][2];
#pragma unroll
            for (int jj = 0; jj < 4; jj++) {
                const uint32_t ad = aW + (uint32_t)((wn + jj*16 + brow) * LDSRH) * 2 + bcb + kb;
                ldsm_x4(b[2*jj][0], b[2*jj][1], b[2*jj+1][0], b[2*jj+1][1], ad);
            }
            uint32_t a[4][4];
#pragma unroll
            for (int i = 0; i < 4; i++) {
                const uint32_t ad = aA + (uint32_t)((wm + i*16 + arow) * LDSRH) * 2 + acb + kb;
                ldsm_x4(a[i][0], a[i][1], a[i][2], a[i][3], ad);
            }
#pragma unroll
            for (int i = 0; i < 4; i++)
#pragma unroll
                for (int j = 0; j < 8; j++)
                    mma_fp16(acc[i][j], a[i], b[j][0], b[j][1]);
        }
        __syncthreads();
    }

    const int er = lane >> 2, ec = (lane & 3) * 2;
#pragma unroll
    for (int i = 0; i < 4; i++)
#pragma unroll
        for (int j = 0; j < 8; j++) {
            float* p0 = C + (size_t)(bm + wm + 16*i + er) * N + bn + wn + 8*j + ec;
            float* p1 = p0 + (size_t)8 * N;
            *(float2*)p0 = make_float2(acc[i][j][0], acc[i][j][1]);
            *(float2*)p1 = make_float2(acc[i][j][2], acc[i][j][3]);
        }
}

// Fused QKV projection: grid (24, 16). bx<16 -> Q, 16..19 -> K, 20..23 -> V.
__global__ __launch_bounds__(256) void gemm_qkv_h(
    const __half* __restrict__ xh,
    const __half* __restrict__ wqh, const __half* __restrict__ wkh,
    const __half* __restrict__ wvh,
    float* __restrict__ q, float* __restrict__ k, float* __restrict__ v)
{
    extern __shared__ char smg[];
    const int bx = blockIdx.x;
    const __half* W;
    float* C;
    int N, bn;
    if (bx < 16)      { W = wqh; C = q; N = NQ_;  bn = bx * 128; }
    else if (bx < 20) { W = wkh; C = k; N = NKV_; bn = (bx - 16) * 128; }
    else              { W = wvh; C = v; N = NKV_; bn = (bx - 20) * 128; }
    gh_core(smg, xh, W, C, N, D_, blockIdx.y * 256, bn);
}

// Generic fp16 GEMM (used for Wo)
__global__ __launch_bounds__(256) void gemm_h_nt(
    const __half* __restrict__ A, const __half* __restrict__ W,
    float* __restrict__ C, int N, int K)
{
    extern __shared__ char smg[];
    gh_core(smg, A, W, C, N, K, blockIdx.y * 256, blockIdx.x * 128);
}

// ---------------------------------------------------------------------------
// RoPE + scale fold + round-to-TF32 in place on q, k, v.
// ---------------------------------------------------------------------------
__global__ __launch_bounds__(256) void rope_tf32(
    float* __restrict__ q, float* __restrict__ k, float* __restrict__ v,
    const float* __restrict__ cosb, const float* __restrict__ sinb,
    const float* __restrict__ temp)
{
    const int token = blockIdx.x;
    const int t = token & (T_ - 1);
    const float SC = 0.08838834764831845f * 1.4426950408889634f;
    for (int s = threadIdx.x; s < 1536; s += blockDim.x) {
        const int head = s >> 6;
        const int i = s & 63;
        float* base;
        float scale = 1.0f;
        bool dorope = true;
        if (head < 16) {
            base = q + ((size_t)token * H_ + head) * DH_;
            scale = temp[head] * SC;
        } else if (head < 20) {
            base = k + ((size_t)token * HKV_ + (head - 16)) * DH_;
        } else {
            base = v + ((size_t)token * HKV_ + (head - 20)) * DH_;
            dorope = false;
        }
        if (dorope && i < 32) {
            const float c  = cosb[t*32 + i];
            const float sn = sinb[t*32 + i];
            const float x1 = base[2*i];
            const float x2 = base[2*i + 1];
            base[2*i]     = tf32r((x1*c - x2*sn) * scale);
            base[2*i + 1] = tf32r((x1*sn + x2*c) * scale);
        } else {
            const int d = dorope ? 64 + (i - 32) * 2 : i * 2;
            base[d]     = tf32r(base[d] * scale);
            base[d + 1] = tf32r(base[d + 1] * scale);
        }
    }
}

// ---------------------------------------------------------------------------
// TF32 tensor-core causal GQA flash attention (proven round-8 kernel;
// epilogue writes fp16 att directly for the Wo GEMM).
// ---------------------------------------------------------------------------
#define KOFF0 0
#define KOFF1 8448
#define VOFF0 16896
#define VOFF1 25600
#define POFF  34304
#define ATTN_SMEM_B ((POFF + 8704) * 4)

__global__ __launch_bounds__(256, 1) void attn_tc(
    const float* __restrict__ Qg, const float* __restrict__ Kg,
    const float* __restrict__ Vg, __half* __restrict__ atth)
{
    extern __shared__ float sm[];
    const uint32_t sbase = (uint32_t)__cvta_generic_to_shared(sm);
    const int qt = 15 - blockIdx.x;
    const int h = blockIdx.y, b = blockIdx.z;
    const int kvh = h >> 2;
    const int tid = threadIdx.x;
    const int warp = tid >> 5, lane = tid & 31;
    const int g4 = lane >> 2, c4 = lane & 3;
    const int qrow0 = qt * 128 + warp * 16;
    const int nk = 2 * qt + 2;

    uint32_t qf[16][4];
    {
        const float* Q0 = Qg + ((size_t)(b*T_ + qrow0 + g4)*H_ + h)*DH_;
        const float* Q1 = Q0 + (size_t)8*H_*DH_;
#pragma unroll
        for (int kc = 0; kc < 16; kc++) {
            const int c0 = kc*8 + c4;
            qf[kc][0] = __float_as_uint(__ldg(Q0 + c0));
            qf[kc][1] = __float_as_uint(__ldg(Q1 + c0));
            qf[kc][2] = __float_as_uint(__ldg(Q0 + c0 + 4));
            qf[kc][3] = __float_as_uint(__ldg(Q1 + c0 + 4));
        }
    }

    float o[16][4];
#pragma unroll
    for (int dt = 0; dt < 16; dt++)
#pragma unroll
        for (int r = 0; r < 4; r++) o[dt][r] = 0.f;
    float m0 = -1e30f, m1 = -1e30f, l0 = 0.f, l1 = 0.f;

    float* Ps = sm + POFF + warp * 1088;

    {
        const size_t kvoff = ((size_t)(b*T_)*HKV_ + kvh)*DH_;
#pragma unroll
        for (int i = 0; i < 8; i++) {
            const int idx = tid + i*256, row = idx >> 5, cc = (idx & 31)*4;
            cp_async16(sbase + (uint32_t)(KOFF0 + row*132 + cc)*4,
                       Kg + kvoff + (size_t)row*NKV_ + cc);
        }
        cp_commit();
#pragma unroll
        for (int i = 0; i < 8; i++) {
            const int idx = tid + i*256, row = idx >> 5, cc = (idx & 31)*4;
            cp_async16(sbase + (uint32_t)(VOFF0 + row*136 + cc)*4,
                       Vg + kvoff + (size_t)row*NKV_ + cc);
        }
        cp_commit();
    }

    for (int kt = 0; kt < nk; kt++) {
        const int kc0 = kt * 64;
        const bool skip = (kc0 > qrow0 + 15);
        cp_wait<1>();
        __syncthreads();

        float sacc[8][4];
        if (!skip) {
#pragma unroll
            for (int nt = 0; nt < 8; nt++)
#pragma unroll
                for (int r = 0; r < 4; r++) sacc[nt][r] = 0.f;
            const float* Ksm = sm + ((kt & 1) ? KOFF1 : KOFF0);
#pragma unroll
            for (int kc = 0; kc < 16; kc++) {
                const int dk = kc*8 + c4;
#pragma unroll
                for (int nt = 0; nt < 8; nt++) {
                    const float* kp = Ksm + (nt*8 + g4)*132 + dk;
                    mma_tf32(sacc[nt], qf[kc],
                             __float_as_uint(kp[0]), __float_as_uint(kp[4]));
                }
            }
        }

        if (kt + 1 < nk) {
            const size_t kvoff = ((size_t)(b*T_ + kc0 + 64)*HKV_ + kvh)*DH_;
            const uint32_t kb = sbase + (uint32_t)(((kt+1)&1) ? KOFF1 : KOFF0)*4;
#pragma unroll
            for (int i = 0; i < 8; i++) {
                const int idx = tid + i*256, row = idx >> 5, cc = (idx & 31)*4;
                cp_async16(kb + (uint32_t)(row*132 + cc)*4,
                           Kg + kvoff + (size_t)row*NKV_ + cc);
            }
            cp_commit();
        }

        if (!skip) {
            if (kc0 + 63 > qrow0) {
#pragma unroll
                for (int nt = 0; nt < 8; nt++) {
                    const int cc = kc0 + nt*8 + 2*c4;
                    const int r0 = qrow0 + g4, r1 = r0 + 8;
                    if (cc     > r0) sacc[nt][0] = -1e30f;
                    if (cc + 1 > r0) sacc[nt][1] = -1e30f;
                    if (cc     > r1) sacc[nt][2] = -1e30f;
                    if (cc + 1 > r1) sacc[nt][3] = -1e30f;
                }
            }
            float rm0 = -1e30f, rm1 = -1e30f;
#pragma unroll
            for (int nt = 0; nt < 8; nt++) {
                rm0 = fmaxf(rm0, fmaxf(sacc[nt][0], sacc[nt][1]));
                rm1 = fmaxf(rm1, fmaxf(sacc[nt][2], sacc[nt][3]));
            }
#pragma unroll
            for (int off = 1; off <= 2; off <<= 1) {
                rm0 = fmaxf(rm0, __shfl_xor_sync(0xffffffffu, rm0, off));
                rm1 = fmaxf(rm1, __shfl_xor_sync(0xffffffffu, rm1, off));
            }
            const float mn0 = fmaxf(m0, rm0), mn1 = fmaxf(m1, rm1);
            const float a0 = fexp2(m0 - mn0), a1 = fexp2(m1 - mn1);
            m0 = mn0; m1 = mn1;
            float rs0 = 0.f, rs1 = 0.f;
#pragma unroll
            for (int nt = 0; nt < 8; nt++) {
                float p0 = fexp2(sacc[nt][0] - mn0);
                float p1 = fexp2(sacc[nt][1] - mn0);
                float p2 = fexp2(sacc[nt][2] - mn1);
                float p3 = fexp2(sacc[nt][3] - mn1);
                rs0 += p0 + p1; rs1 += p2 + p3;
                float* pr = Ps + g4*68 + nt*8 + 2*c4;
                *(float2*)pr = make_float2(__uint_as_float(f2tf32(p0)),
                                           __uint_as_float(f2tf32(p1)));
                *(float2*)(pr + 8*68) = make_float2(__uint_as_float(f2tf32(p2)),
                                                    __uint_as_float(f2tf32(p3)));
            }
#pragma unroll
            for (int off = 1; off <= 2; off <<= 1) {
                rs0 += __shfl_xor_sync(0xffffffffu, rs0, off);
                rs1 += __shfl_xor_sync(0xffffffffu, rs1, off);
            }
            l0 = l0 * a0 + rs0;
            l1 = l1 * a1 + rs1;
#pragma unroll
            for (int dt = 0; dt < 16; dt++) {
                o[dt][0] *= a0; o[dt][1] *= a0;
                o[dt][2] *= a1; o[dt][3] *= a1;
            }
        }

        if (kt + 1 < nk) cp_wait<1>(); else cp_wait<0>();
        __syncthreads();

        if (!skip) {
            const float* Vsm = sm + ((kt & 1) ? VOFF1 : VOFF0);
#pragma unroll
            for (int kc = 0; kc < 8; kc++) {
                uint32_t af[4];
                const float* pr = Ps + g4*68 + kc*8 + c4;
                af[0] = __float_as_uint(pr[0]);
                af[1] = __float_as_uint(pr[8*68]);
                af[2] = __float_as_uint(pr[4]);
                af[3] = __float_as_uint(pr[8*68 + 4]);
#pragma unroll
                for (int dt = 0; dt < 16; dt++) {
                    const float* vp = Vsm + (kc*8 + c4)*136 + dt*8 + g4;
                    mma_tf32(o[dt], af,
                             __float_as_uint(vp[0]), __float_as_uint(vp[4*136]));
                }
            }
        }

        if (kt + 1 < nk) {
            const size_t kvoff = ((size_t)(b*T_ + kc0 + 64)*HKV_ + kvh)*DH_;
            const uint32_t vb = sbase + (uint32_t)(((kt+1)&1) ? VOFF1 : VOFF0)*4;
#pragma unroll
            for (int i = 0; i < 8; i++) {
                const int idx = tid + i*256, row = idx >> 5, cc = (idx & 31)*4;
                cp_async16(vb + (uint32_t)(row*136 + cc)*4,
                           Vg + kvoff + (size_t)row*NKV_ + cc);
            }
            cp_commit();
        }
    }

    // epilogue: /l, write fp16 att for the Wo fp16 GEMM
    const float inv0 = 1.f / l0, inv1 = 1.f / l1;
    __half* r0 = atth + ((size_t)(b*T_ + qrow0 + g4))*NQ_ + h*DH_ + 2*c4;
    __half* r1 = r0 + (size_t)8*NQ_;
#pragma unroll
    for (int dt = 0; dt < 16; dt++) {
        *(__half2*)(r0 + dt*8) = __floats2half2_rn(o[dt][0]*inv0, o[dt][1]*inv0);
        *(__half2*)(r1 + dt*8) = __floats2half2_rn(o[dt][2]*inv1, o[dt][3]*inv1);
    }
}

// ---------------------------------------------------------------------------
extern "C" void kernel_launch(void* const* d_in, const int* in_sizes, int n_in,
                              void* d_out, int out_size)
{
    const float* x    = (const float*)d_in[0];
    const float* cosb = (const float*)d_in[1];
    const float* sinb = (const float*)d_in[2];
    const float* Wq   = (const float*)d_in[3];
    const float* Wk   = (const float*)d_in[4];
    const float* Wv   = (const float*)d_in[5];
    const float* Wo   = (const float*)d_in[6];
    const float* temp = (const float*)d_in[7];
    float* out = (float*)d_out;

    float *q, *k, *v;
    cudaGetSymbolAddress((void**)&q, g_q);
    cudaGetSymbolAddress((void**)&k, g_k);
    cudaGetSymbolAddress((void**)&v, g_v);

    __half *xh, *wqh, *wkh, *wvh, *woh, *atth;
    cudaGetSymbolAddress((void**)&xh,   g_xh);
    cudaGetSymbolAddress((void**)&wqh,  g_wqh);
    cudaGetSymbolAddress((void**)&wkh,  g_wkh);
    cudaGetSymbolAddress((void**)&wvh,  g_wvh);
    cudaGetSymbolAddress((void**)&woh,  g_woh);
    cudaGetSymbolAddress((void**)&atth, g_atth);

    cudaFuncSetAttribute(gemm_qkv_h,
                         cudaFuncAttributeMaxDynamicSharedMemorySize, GEMMH_SMEM);
    cudaFuncSetAttribute(gemm_h_nt,
                         cudaFuncAttributeMaxDynamicSharedMemorySize, GEMMH_SMEM);
    cudaFuncSetAttribute(attn_tc,
                         cudaFuncAttributeMaxDynamicSharedMemorySize, ATTN_SMEM_B);

    // Convert operands to fp16
    h16_kernel<<<(M_*D_ + 255)/256,   256>>>(x,  xh,  M_*D_);
    h16_kernel<<<(NQ_*D_ + 255)/256,  256>>>(Wq, wqh, NQ_*D_);
    h16_kernel<<<(NKV_*D_ + 255)/256, 256>>>(Wk, wkh, NKV_*D_);
    h16_kernel<<<(NKV_*D_ + 255)/256, 256>>>(Wv, wvh, NKV_*D_);
    h16_kernel<<<(D_*D_ + 255)/256,   256>>>(Wo, woh, D_*D_);

    // QKV projections (single-pass fp16 k16 tensor cores, fused, 256x128 tiles)
    gemm_qkv_h<<<dim3(24, M_/256), 256, GEMMH_SMEM>>>(
        xh, wqh, wkh, wvh, q, k, v);

    // RoPE + temp + tf32 round
    rope_tf32<<<M_, 256>>>(q, k, v, cosb, sinb, temp);

    // Flash attention (TF32 tensor cores), fp16 epilogue
    attn_tc<<<dim3(16, H_, B_), 256, ATTN_SMEM_B>>>(q, k, v, atth);

    // Output projection (single-pass fp16, 256x128 tiles)
    gemm_h_nt<<<dim3(D_/128, M_/256), 256, GEMMH_SMEM>>>(atth, woh, out, D_, D_);
}

// round 16
// speedup vs baseline: 3.4199x; 1.2275x over previous
#include <cuda_runtime.h>
#include <cuda_fp16.h>
#include <cstdint>

// Problem constants
#define B_  2
#define T_  2048
#define D_  2048
#define H_  16
#define HKV_ 4
#define DH_ 128
#define M_  (B_*T_)
#define NQ_ (H_*DH_)
#define NKV_ (HKV_*DH_)

// fp32 scratch (GEMM outputs)
__device__ float g_q[(size_t)M_ * NQ_];
__device__ float g_k[(size_t)M_ * NKV_];
__device__ float g_v[(size_t)M_ * NKV_];
// fp16 operands
__device__ __half g_xh[(size_t)M_ * D_];
__device__ __half g_wqh[(size_t)NQ_ * D_];
__device__ __half g_wkh[(size_t)NKV_ * D_];
__device__ __half g_wvh[(size_t)NKV_ * D_];
__device__ __half g_woh[(size_t)D_ * D_];
__device__ __half g_atth[(size_t)M_ * NQ_];
// fp16 post-rope q/k/v
__device__ __half g_qh[(size_t)M_ * NQ_];
__device__ __half g_kh[(size_t)M_ * NKV_];
__device__ __half g_vh[(size_t)M_ * NKV_];

// ---------------------------------------------------------------------------
// PTX helpers (compute_103-safe)
// ---------------------------------------------------------------------------
__device__ __forceinline__ void cp_async16(uint32_t s, const void* g) {
    asm volatile("cp.async.cg.shared.global [%0], [%1], 16;\n" :: "r"(s), "l"(g));
}
__device__ __forceinline__ void cp_commit() {
    asm volatile("cp.async.commit_group;\n");
}
template<int N> __device__ __forceinline__ void cp_wait() {
    asm volatile("cp.async.wait_group %0;\n" :: "n"(N));
}
__device__ __forceinline__ void ldsm_x4(uint32_t& r0, uint32_t& r1,
                                        uint32_t& r2, uint32_t& r3, uint32_t a) {
    asm volatile("ldmatrix.sync.aligned.m8n8.x4.shared.b16 {%0,%1,%2,%3}, [%4];\n"
                 : "=r"(r0), "=r"(r1), "=r"(r2), "=r"(r3) : "r"(a));
}
__device__ __forceinline__ void ldsm_x4_t(uint32_t& r0, uint32_t& r1,
                                          uint32_t& r2, uint32_t& r3, uint32_t a) {
    asm volatile("ldmatrix.sync.aligned.m8n8.x4.trans.shared.b16 {%0,%1,%2,%3}, [%4];\n"
                 : "=r"(r0), "=r"(r1), "=r"(r2), "=r"(r3) : "r"(a));
}
__device__ __forceinline__ void mma_fp16(float* d, const uint32_t* a,
                                         uint32_t b0, uint32_t b1) {
    asm volatile(
        "mma.sync.aligned.m16n8k16.row.col.f32.f16.f16.f32 "
        "{%0,%1,%2,%3},{%4,%5,%6,%7},{%8,%9},{%0,%1,%2,%3};\n"
        : "+f"(d[0]), "+f"(d[1]), "+f"(d[2]), "+f"(d[3])
        : "r"(a[0]), "r"(a[1]), "r"(a[2]), "r"(a[3]), "r"(b0), "r"(b1));
}
__device__ __forceinline__ float fexp2(float x) {
    float y;
    asm("ex2.approx.ftz.f32 %0, %1;" : "=f"(y) : "f"(x));
    return y;
}

// ---------------------------------------------------------------------------
// Convert fp32 -> fp16 (rn)
// ---------------------------------------------------------------------------
__global__ __launch_bounds__(256) void h16_kernel(
    const float* __restrict__ in, __half* __restrict__ out, int n)
{
    int i = blockIdx.x * blockDim.x + threadIdx.x;
    if (i < n) out[i] = __float2half_rn(in[i]);
}

// ---------------------------------------------------------------------------
// fp16 NT GEMM core (proven R15): 256x128 tile, BK=64, 8 warps 4x2,
// warp tile 64x64, mma.m16n8k16.f16, 2-stage cp.async, 144B row stride.
// ---------------------------------------------------------------------------
#define BK_H     64
#define LDSRH    72
#define TILE_AH  (256*LDSRH*2)
#define TILE_WH  (128*LDSRH*2)
#define STAGE_H  (TILE_AH + TILE_WH)
#define GEMMH_SMEM (2*STAGE_H)

__device__ __forceinline__ void gh_load_stage(
    uint32_t sa, const __half* __restrict__ A, const __half* __restrict__ W,
    int bm, int bn, int K, int k0, int tid)
{
#pragma unroll
    for (int t = 0; t < 8; t++) {
        const int idx = tid + t * 256;
        const int row = idx >> 3;
        const int c8  = (idx & 7) * 8;
        cp_async16(sa + (uint32_t)(row * LDSRH + c8) * 2,
                   A + (size_t)(bm + row) * K + k0 + c8);
    }
#pragma unroll
    for (int t = 0; t < 4; t++) {
        const int idx = tid + t * 256;
        const int row = idx >> 3;
        const int c8  = (idx & 7) * 8;
        cp_async16(sa + (uint32_t)TILE_AH + (uint32_t)(row * LDSRH + c8) * 2,
                   W + (size_t)(bn + row) * K + k0 + c8);
    }
}

__device__ __forceinline__ void gh_core(
    char* smg, const __half* __restrict__ A, const __half* __restrict__ W,
    float* __restrict__ C, int N, int K, int bm, int bn)
{
    const int tid  = threadIdx.x;
    const int warp = tid >> 5, lane = tid & 31;
    const int wm = (warp >> 1) * 64;
    const int wn = (warp & 1) * 64;
    const uint32_t sbase = (uint32_t)__cvta_generic_to_shared(smg);

    float acc[4][8][4];
#pragma unroll
    for (int i = 0; i < 4; i++)
#pragma unroll
        for (int j = 0; j < 8; j++)
#pragma unroll
            for (int r = 0; r < 4; r++) acc[i][j][r] = 0.f;

    const int arow = (lane & 7) + ((lane >> 3) & 1) * 8;
    const int acb  = ((lane >> 4) & 1) * 16;
    const int brow = (lane & 7) + ((lane >> 4) & 1) * 8;
    const int bcb  = ((lane >> 3) & 1) * 16;

    gh_load_stage(sbase, A, W, bm, bn, K, 0, tid);
    cp_commit();

    const int NC = K / BK_H;
    for (int c = 0; c < NC; c++) {
        if (c + 1 < NC) {
            gh_load_stage(sbase + ((c + 1) & 1) * STAGE_H,
                          A, W, bm, bn, K, (c + 1) * BK_H, tid);
            cp_commit();
            cp_wait<1>();
        } else {
            cp_wait<0>();
        }
        __syncthreads();

        const uint32_t aA = sbase + (c & 1) * STAGE_H;
        const uint32_t aW = aA + TILE_AH;

#pragma unroll
        for (int ks = 0; ks < 4; ks++) {
            const int kb = ks * 32;
            uint32_t b[8][2];
#pragma unroll
            for (int jj = 0; jj < 4; jj++) {
                const uint32_t ad = aW + (uint32_t)((wn + jj*16 + brow) * LDSRH) * 2 + bcb + kb;
                ldsm_x4(b[2*jj][0], b[2*jj][1], b[2*jj+1][0], b[2*jj+1][1], ad);
            }
            uint32_t a[4][4];
#pragma unroll
            for (int i = 0; i < 4; i++) {
                const uint32_t ad = aA + (uint32_t)((wm + i*16 + arow) * LDSRH) * 2 + acb + kb;
                ldsm_x4(a[i][0], a[i][1], a[i][2], a[i][3], ad);
            }
#pragma unroll
            for (int i = 0; i < 4; i++)
#pragma unroll
                for (int j = 0; j < 8; j++)
                    mma_fp16(acc[i][j], a[i], b[j][0], b[j][1]);
        }
        __syncthreads();
    }

    const int er = lane >> 2, ec = (lane & 3) * 2;
#pragma unroll
    for (int i = 0; i < 4; i++)
#pragma unroll
        for (int j = 0; j < 8; j++) {
            float* p0 = C + (size_t)(bm + wm + 16*i + er) * N + bn + wn + 8*j + ec;
            float* p1 = p0 + (size_t)8 * N;
            *(float2*)p0 = make_float2(acc[i][j][0], acc[i][j][1]);
            *(float2*)p1 = make_float2(acc[i][j][2], acc[i][j][3]);
        }
}

__global__ __launch_bounds__(256) void gemm_qkv_h(
    const __half* __restrict__ xh,
    const __half* __restrict__ wqh, const __half* __restrict__ wkh,
    const __half* __restrict__ wvh,
    float* __restrict__ q, float* __restrict__ k, float* __restrict__ v)
{
    extern __shared__ char smg[];
    const int bx = blockIdx.x;
    const __half* W;
    float* C;
    int N, bn;
    if (bx < 16)      { W = wqh; C = q; N = NQ_;  bn = bx * 128; }
    else if (bx < 20) { W = wkh; C = k; N = NKV_; bn = (bx - 16) * 128; }
    else              { W = wvh; C = v; N = NKV_; bn = (bx - 20) * 128; }
    gh_core(smg, xh, W, C, N, D_, blockIdx.y * 256, bn);
}

__global__ __launch_bounds__(256) void gemm_h_nt(
    const __half* __restrict__ A, const __half* __restrict__ W,
    float* __restrict__ C, int N, int K)
{
    extern __shared__ char smg[];
    gh_core(smg, A, W, C, N, K, blockIdx.y * 256, blockIdx.x * 128);
}

// ---------------------------------------------------------------------------
// RoPE + scale fold; fp32 in -> fp16 out (qh/kh/vh).
// ---------------------------------------------------------------------------
__global__ __launch_bounds__(256) void rope_h(
    const float* __restrict__ q, const float* __restrict__ k,
    const float* __restrict__ v,
    __half* __restrict__ qh, __half* __restrict__ kh, __half* __restrict__ vh,
    const float* __restrict__ cosb, const float* __restrict__ sinb,
    const float* __restrict__ temp)
{
    const int token = blockIdx.x;
    const int t = token & (T_ - 1);
    const float SC = 0.08838834764831845f * 1.4426950408889634f;
    for (int s = threadIdx.x; s < 1536; s += blockDim.x) {
        const int head = s >> 6;
        const int i = s & 63;
        const float* src;
        __half* dst;
        float scale = 1.0f;
        bool dorope = true;
        if (head < 16) {
            src = q + ((size_t)token * H_ + head) * DH_;
            dst = qh + ((size_t)token * H_ + head) * DH_;
            scale = temp[head] * SC;
        } else if (head < 20) {
            src = k + ((size_t)token * HKV_ + (head - 16)) * DH_;
            dst = kh + ((size_t)token * HKV_ + (head - 16)) * DH_;
        } else {
            src = v + ((size_t)token * HKV_ + (head - 20)) * DH_;
            dst = vh + ((size_t)token * HKV_ + (head - 20)) * DH_;
            dorope = false;
        }
        if (dorope && i < 32) {
            const float c  = cosb[t*32 + i];
            const float sn = sinb[t*32 + i];
            const float x1 = src[2*i];
            const float x2 = src[2*i + 1];
            *(__half2*)(dst + 2*i) =
                __floats2half2_rn((x1*c - x2*sn) * scale, (x1*sn + x2*c) * scale);
        } else {
            const int d = dorope ? 64 + (i - 32) * 2 : i * 2;
            *(__half2*)(dst + d) =
                __floats2half2_rn(src[d] * scale, src[d + 1] * scale);
        }
    }
}

// ---------------------------------------------------------------------------
// fp16 tensor-core causal GQA flash attention.
// BQ=128 (8 warps x 16 rows), BK=64, DH=128.
// K/V fp16 double-buffered (136-half rows), P fp16 smem (72-half rows).
// QK B-frags: direct half2 LDS. PV B-frags: ldmatrix.x4.trans.
// ---------------------------------------------------------------------------
#define KH0   0
#define KH1   8704
#define VH0   17408
#define VH1   26112
#define PH0   34816                      // halves; per-warp stride 1152
#define ATTN_SMEM_B ((PH0 + 8*1152) * 2) // 88064 bytes

__global__ __launch_bounds__(256, 1) void attn_h(
    const __half* __restrict__ Qg, const __half* __restrict__ Kg,
    const __half* __restrict__ Vg, __half* __restrict__ atth)
{
    extern __shared__ __half smh[];
    const uint32_t sbase = (uint32_t)__cvta_generic_to_shared(smh);
    const int qt = 15 - blockIdx.x;
    const int h = blockIdx.y, b = blockIdx.z;
    const int kvh = h >> 2;
    const int tid = threadIdx.x;
    const int warp = tid >> 5, lane = tid & 31;
    const int g4 = lane >> 2, c4 = lane & 3;
    const int qrow0 = qt * 128 + warp * 16;
    const int nk = 2 * qt + 2;

    // Q fragments (fp16, from rope output)
    uint32_t qf[8][4];
    {
        const __half* Q0 = Qg + ((size_t)(b*T_ + qrow0 + g4)*H_ + h)*DH_;
        const __half* Q1 = Q0 + (size_t)8*H_*DH_;
#pragma unroll
        for (int kc = 0; kc < 8; kc++) {
            const int c0 = kc*16 + 2*c4;
            qf[kc][0] = *(const uint32_t*)(Q0 + c0);
            qf[kc][1] = *(const uint32_t*)(Q1 + c0);
            qf[kc][2] = *(const uint32_t*)(Q0 + c0 + 8);
            qf[kc][3] = *(const uint32_t*)(Q1 + c0 + 8);
        }
    }

    float o[16][4];
#pragma unroll
    for (int dt = 0; dt < 16; dt++)
#pragma unroll
        for (int r = 0; r < 4; r++) o[dt][r] = 0.f;
    float m0 = -1e30f, m1 = -1e30f, l0 = 0.f, l1 = 0.f;

    __half* Ph = smh + PH0 + warp * 1152;

    // prologue: K0, V0 (each 64 x 128 fp16 = 1024 x 16B)
    {
        const size_t kvoff = ((size_t)(b*T_)*HKV_ + kvh)*DH_;
#pragma unroll
        for (int i = 0; i < 4; i++) {
            const int idx = tid + i*256, row = idx >> 4, c8 = (idx & 15)*8;
            cp_async16(sbase + (uint32_t)(KH0 + row*136 + c8)*2,
                       Kg + kvoff + (size_t)row*NKV_ + c8);
        }
        cp_commit();
#pragma unroll
        for (int i = 0; i < 4; i++) {
            const int idx = tid + i*256, row = idx >> 4, c8 = (idx & 15)*8;
            cp_async16(sbase + (uint32_t)(VH0 + row*136 + c8)*2,
                       Vg + kvoff + (size_t)row*NKV_ + c8);
        }
        cp_commit();
    }

    for (int kt = 0; kt < nk; kt++) {
        const int kc0 = kt * 64;
        const bool skip = (kc0 > qrow0 + 15);
        cp_wait<1>();
        __syncthreads();

        float sacc[8][4];
        if (!skip) {
#pragma unroll
            for (int nt = 0; nt < 8; nt++)
#pragma unroll
                for (int r = 0; r < 4; r++) sacc[nt][r] = 0.f;
            const __half* Ksm = smh + ((kt & 1) ? KH1 : KH0);
#pragma unroll
            for (int kc = 0; kc < 8; kc++) {
#pragma unroll
                for (int nt = 0; nt < 8; nt++) {
                    const __half* kp = Ksm + (nt*8 + g4)*136 + kc*16 + 2*c4;
                    mma_fp16(sacc[nt], qf[kc],
                             *(const uint32_t*)kp, *(const uint32_t*)(kp + 8));
                }
            }
        }

        if (kt + 1 < nk) {   // prefetch next K
            const size_t kvoff = ((size_t)(b*T_ + kc0 + 64)*HKV_ + kvh)*DH_;
            const uint32_t kb = sbase + (uint32_t)(((kt+1)&1) ? KH1 : KH0)*2;
#pragma unroll
            for (int i = 0; i < 4; i++) {
                const int idx = tid + i*256, row = idx >> 4, c8 = (idx & 15)*8;
                cp_async16(kb + (uint32_t)(row*136 + c8)*2,
                           Kg + kvoff + (size_t)row*NKV_ + c8);
            }
            cp_commit();
        }

        if (!skip) {
            if (kc0 + 63 > qrow0) {
#pragma unroll
                for (int nt = 0; nt < 8; nt++) {
                    const int cc = kc0 + nt*8 + 2*c4;
                    const int r0 = qrow0 + g4, r1 = r0 + 8;
                    if (cc     > r0) sacc[nt][0] = -1e30f;
                    if (cc + 1 > r0) sacc[nt][1] = -1e30f;
                    if (cc     > r1) sacc[nt][2] = -1e30f;
                    if (cc + 1 > r1) sacc[nt][3] = -1e30f;
                }
            }
            float rm0 = -1e30f, rm1 = -1e30f;
#pragma unroll
            for (int nt = 0; nt < 8; nt++) {
                rm0 = fmaxf(rm0, fmaxf(sacc[nt][0], sacc[nt][1]));
                rm1 = fmaxf(rm1, fmaxf(sacc[nt][2], sacc[nt][3]));
            }
#pragma unroll
            for (int off = 1; off <= 2; off <<= 1) {
                rm0 = fmaxf(rm0, __shfl_xor_sync(0xffffffffu, rm0, off));
                rm1 = fmaxf(rm1, __shfl_xor_sync(0xffffffffu, rm1, off));
            }
            const float mn0 = fmaxf(m0, rm0), mn1 = fmaxf(m1, rm1);
            const float a0 = fexp2(m0 - mn0), a1 = fexp2(m1 - mn1);
            m0 = mn0; m1 = mn1;
            float rs0 = 0.f, rs1 = 0.f;
#pragma unroll
            for (int nt = 0; nt < 8; nt++) {
                float p0 = fexp2(sacc[nt][0] - mn0);
                float p1 = fexp2(sacc[nt][1] - mn0);
                float p2 = fexp2(sacc[nt][2] - mn1);
                float p3 = fexp2(sacc[nt][3] - mn1);
                rs0 += p0 + p1; rs1 += p2 + p3;
                __half* pr = Ph + g4*72 + nt*8 + 2*c4;
                *(__half2*)pr          = __floats2half2_rn(p0, p1);
                *(__half2*)(pr + 8*72) = __floats2half2_rn(p2, p3);
            }
#pragma unroll
            for (int off = 1; off <= 2; off <<= 1) {
                rs0 += __shfl_xor_sync(0xffffffffu, rs0, off);
                rs1 += __shfl_xor_sync(0xffffffffu, rs1, off);
            }
            l0 = l0 * a0 + rs0;
            l1 = l1 * a1 + rs1;
#pragma unroll
            for (int dt = 0; dt < 16; dt++) {
                o[dt][0] *= a0; o[dt][1] *= a0;
                o[dt][2] *= a1; o[dt][3] *= a1;
            }
        }

        if (kt + 1 < nk) cp_wait<1>(); else cp_wait<0>();
        __syncthreads();

        if (!skip) {
            const uint32_t vbase = sbase + (uint32_t)(((kt & 1) ? VH1 : VH0))*2;
            const int lm  = lane >> 3;           // matrix index 0..3
            const int lim = lane & 7;
#pragma unroll
            for (int kc = 0; kc < 4; kc++) {
                uint32_t af[4];
                const __half* pa = Ph + g4*72 + kc*16 + 2*c4;
                af[0] = *(const uint32_t*)pa;
                af[1] = *(const uint32_t*)(pa + 8*72);
                af[2] = *(const uint32_t*)(pa + 8);
                af[3] = *(const uint32_t*)(pa + 8*72 + 8);
#pragma unroll
                for (int dp = 0; dp < 8; dp++) {
                    const int vrow = kc*16 + (lm & 1)*8 + lim;
                    const int vcol = dp*16 + (lm >> 1)*8;
                    uint32_t b0, b1, b2, b3;
                    ldsm_x4_t(b0, b1, b2, b3,
                              vbase + (uint32_t)(vrow*136 + vcol)*2);
                    mma_fp16(o[2*dp],     af, b0, b1);
                    mma_fp16(o[2*dp + 1], af, b2, b3);
                }
            }
        }

        if (kt + 1 < nk) {   // prefetch next V
            const size_t kvoff = ((size_t)(b*T_ + kc0 + 64)*HKV_ + kvh)*DH_;
            const uint32_t vb = sbase + (uint32_t)(((kt+1)&1) ? VH1 : VH0)*2;
#pragma unroll
            for (int i = 0; i < 4; i++) {
                const int idx = tid + i*256, row = idx >> 4, c8 = (idx & 15)*8;
                cp_async16(vb + (uint32_t)(row*136 + c8)*2,
                           Vg + kvoff + (size_t)row*NKV_ + c8);
            }
            cp_commit();
        }
    }

    // epilogue: /l, write fp16 att for the Wo fp16 GEMM
    const float inv0 = 1.f / l0, inv1 = 1.f / l1;
    __half* r0 = atth + ((size_t)(b*T_ + qrow0 + g4))*NQ_ + h*DH_ + 2*c4;
    __half* r1 = r0 + (size_t)8*NQ_;
#pragma unroll
    for (int dt = 0; dt < 16; dt++) {
        *(__half2*)(r0 + dt*8) = __floats2half2_rn(o[dt][0]*inv0, o[dt][1]*inv0);
        *(__half2*)(r1 + dt*8) = __floats2half2_rn(o[dt][2]*inv1, o[dt][3]*inv1);
    }
}

// ---------------------------------------------------------------------------
extern "C" void kernel_launch(void* const* d_in, const int* in_sizes, int n_in,
                              void* d_out, int out_size)
{
    const float* x    = (const float*)d_in[0];
    const float* cosb = (const float*)d_in[1];
    const float* sinb = (const float*)d_in[2];
    const float* Wq   = (const float*)d_in[3];
    const float* Wk   = (const float*)d_in[4];
    const float* Wv   = (const float*)d_in[5];
    const float* Wo   = (const float*)d_in[6];
    const float* temp = (const float*)d_in[7];
    float* out = (float*)d_out;

    float *q, *k, *v;
    cudaGetSymbolAddress((void**)&q, g_q);
    cudaGetSymbolAddress((void**)&k, g_k);
    cudaGetSymbolAddress((void**)&v, g_v);

    __half *xh, *wqh, *wkh, *wvh, *woh, *atth, *qh, *kh, *vh;
    cudaGetSymbolAddress((void**)&xh,   g_xh);
    cudaGetSymbolAddress((void**)&wqh,  g_wqh);
    cudaGetSymbolAddress((void**)&wkh,  g_wkh);
    cudaGetSymbolAddress((void**)&wvh,  g_wvh);
    cudaGetSymbolAddress((void**)&woh,  g_woh);
    cudaGetSymbolAddress((void**)&atth, g_atth);
    cudaGetSymbolAddress((void**)&qh,   g_qh);
    cudaGetSymbolAddress((void**)&kh,   g_kh);
    cudaGetSymbolAddress((void**)&vh,   g_vh);

    cudaFuncSetAttribute(gemm_qkv_h,
                         cudaFuncAttributeMaxDynamicSharedMemorySize, GEMMH_SMEM);
    cudaFuncSetAttribute(gemm_h_nt,
                         cudaFuncAttributeMaxDynamicSharedMemorySize, GEMMH_SMEM);
    cudaFuncSetAttribute(attn_h,
                         cudaFuncAttributeMaxDynamicSharedMemorySize, ATTN_SMEM_B);

    // Convert operands to fp16
    h16_kernel<<<(M_*D_ + 255)/256,   256>>>(x,  xh,  M_*D_);
    h16_kernel<<<(NQ_*D_ + 255)/256,  256>>>(Wq, wqh, NQ_*D_);
    h16_kernel<<<(NKV_*D_ + 255)/256, 256>>>(Wk, wkh, NKV_*D_);
    h16_kernel<<<(NKV_*D_ + 255)/256, 256>>>(Wv, wvh, NKV_*D_);
    h16_kernel<<<(D_*D_ + 255)/256,   256>>>(Wo, woh, D_*D_);

    // QKV projections (fp16 k16 tensor cores, fused, 256x128 tiles)
    gemm_qkv_h<<<dim3(24, M_/256), 256, GEMMH_SMEM>>>(
        xh, wqh, wkh, wvh, q, k, v);

    // RoPE + temp, fp32 -> fp16
    rope_h<<<M_, 256>>>(q, k, v, qh, kh, vh, cosb, sinb, temp);

    // Flash attention (fp16 tensor cores), fp16 epilogue
    attn_h<<<dim3(16, H_, B_), 256, ATTN_SMEM_B>>>(qh, kh, vh, atth);

    // Output projection (fp16, 256x128 tiles)
    gemm_h_nt<<<dim3(D_/128, M_/256), 256, GEMMH_SMEM>>>(atth, woh, out, D_, D_);
}